// round 6
// baseline (speedup 1.0000x reference)
#include <cuda_runtime.h>
#include <math.h>

typedef unsigned long long ull;

// ---------- device scratch (no allocations allowed) ----------
__device__ float g_eo[128 * 64];
__device__ float g_ed[128 * 64];
__device__ float g_spair[16384];
__device__ float g_part[128];

// ---------- helpers ----------
__device__ __forceinline__ ull pk2(float a) {
    ull r; asm("mov.b64 %0, {%1, %1};" : "=l"(r) : "f"(a)); return r;
}
__device__ __forceinline__ ull f2fma(ull a, ull b, ull c) {
    ull d; asm("fma.rn.f32x2 %0, %1, %2, %3;" : "=l"(d) : "l"(a), "l"(b), "l"(c)); return d;
}
__device__ __forceinline__ float2 upk(ull v) {
    float2 r; asm("mov.b64 {%0, %1}, %2;" : "=f"(r.x), "=f"(r.y) : "l"(v)); return r;
}
__device__ __forceinline__ float sigf(float v) {
    return __fdividef(1.0f, 1.0f + __expf(-v));
}
__device__ __forceinline__ float tanhe(float v) {
    return __fdividef(2.0f, 1.0f + __expf(-2.0f * v)) - 1.0f;
}

// accumulate 3 gates x 4 f32x2 lanes from one 192-wide weight row
#define ACC3(ROWPTR, XV, AR, AZ, AN) do {                                   \
    const ulonglong2* _p0 = (const ulonglong2*)(ROWPTR);                    \
    ulonglong2 _w0 = _p0[0], _w1 = _p0[1];                                  \
    const ulonglong2* _p1 = (const ulonglong2*)((ROWPTR) + 64);             \
    ulonglong2 _z0 = _p1[0], _z1 = _p1[1];                                  \
    const ulonglong2* _p2 = (const ulonglong2*)((ROWPTR) + 128);            \
    ulonglong2 _n0 = _p2[0], _n1 = _p2[1];                                  \
    AR[0] = f2fma(XV, _w0.x, AR[0]); AR[1] = f2fma(XV, _w0.y, AR[1]);       \
    AR[2] = f2fma(XV, _w1.x, AR[2]); AR[3] = f2fma(XV, _w1.y, AR[3]);       \
    AZ[0] = f2fma(XV, _z0.x, AZ[0]); AZ[1] = f2fma(XV, _z0.y, AZ[1]);       \
    AZ[2] = f2fma(XV, _z1.x, AZ[2]); AZ[3] = f2fma(XV, _z1.y, AZ[3]);       \
    AN[0] = f2fma(XV, _n0.x, AN[0]); AN[1] = f2fma(XV, _n0.y, AN[1]);       \
    AN[2] = f2fma(XV, _n1.x, AN[2]); AN[3] = f2fma(XV, _n1.y, AN[3]);       \
} while (0)

// ---------- node encoders: 256 blocks (128 O rows + 128 D rows) ----------
__global__ void __launch_bounds__(128) enc_kernel(
    const float* __restrict__ Of, const float* __restrict__ Df,
    const float* __restrict__ WO1, const float* __restrict__ bO1,
    const float* __restrict__ WO2, const float* __restrict__ bO2,
    const float* __restrict__ WO3, const float* __restrict__ bO3,
    const float* __restrict__ WD1, const float* __restrict__ bD1,
    const float* __restrict__ WD2, const float* __restrict__ bD2,
    const float* __restrict__ WD3, const float* __restrict__ bD3)
{
    __shared__ float fs[64], h1[128], h2[128];
    int b = blockIdx.x;
    int row = b & 127;
    bool isD = (b >= 128);
    const float* feats = isD ? Df : Of;
    const float* W1 = isD ? WD1 : WO1; const float* b1 = isD ? bD1 : bO1;
    const float* W2 = isD ? WD2 : WO2; const float* b2 = isD ? bD2 : bO2;
    const float* W3 = isD ? WD3 : WO3; const float* b3 = isD ? bD3 : bO3;
    float* out = isD ? g_ed : g_eo;
    int tid = threadIdx.x;

    if (tid < 64) fs[tid] = feats[row * 64 + tid];
    __syncthreads();

    float a = b1[tid];
    #pragma unroll 8
    for (int i = 0; i < 64; ++i) a = fmaf(fs[i], W1[i * 128 + tid], a);
    h1[tid] = fmaxf(a, 0.f);
    __syncthreads();

    a = b2[tid];
    #pragma unroll 8
    for (int i = 0; i < 128; ++i) a = fmaf(h1[i], W2[i * 128 + tid], a);
    h2[tid] = fmaxf(a, 0.f);
    __syncthreads();

    if (tid < 64) {
        a = b3[tid];
        #pragma unroll 8
        for (int i = 0; i < 128; ++i) a = fmaf(h2[i], W3[i * 64 + tid], a);
        out[row * 64 + tid] = a;
    }
}

// ---------- pair head: 128 blocks (o) x 128 threads (d) ----------
// hp[kc] = relu(ao[kc] + sum_i ed[i]*Wp1[64+i][kc] + b1[kc]);  z = hp.Wp2 + b2
// ao[kc] (the eo part) is computed once per block.
__global__ void __launch_bounds__(128) pair_kernel(
    const float* __restrict__ Wp1, const float* __restrict__ bp1,
    const float* __restrict__ Wp2, const float* __restrict__ bp2)
{
    __shared__ float ao[128], sb[128], sw2[128], seo[64];
    int tid = threadIdx.x, o = blockIdx.x;
    sb[tid] = bp1[tid];
    sw2[tid] = Wp2[tid];
    if (tid < 64) seo[tid] = g_eo[o * 64 + tid];
    __syncthreads();

    float a = 0.f;
    #pragma unroll 8
    for (int i = 0; i < 64; ++i) a = fmaf(seo[i], Wp1[i * 128 + tid], a);
    ao[tid] = a;
    __syncthreads();

    float ed[64];
    const float4* edp = (const float4*)(g_ed + tid * 64);
    #pragma unroll
    for (int q = 0; q < 16; ++q) {
        float4 v = edp[q];
        ed[4*q] = v.x; ed[4*q+1] = v.y; ed[4*q+2] = v.z; ed[4*q+3] = v.w;
    }

    float z = bp2[0];
    #pragma unroll 1
    for (int kc = 0; kc < 128; kc += 4) {
        float4 acc = make_float4(ao[kc] + sb[kc], ao[kc+1] + sb[kc+1],
                                 ao[kc+2] + sb[kc+2], ao[kc+3] + sb[kc+3]);
        #pragma unroll
        for (int i = 0; i < 64; ++i) {
            float e = ed[i];
            float4 w = *(const float4*)&Wp1[(64 + i) * 128 + kc];
            acc.x = fmaf(e, w.x, acc.x); acc.y = fmaf(e, w.y, acc.y);
            acc.z = fmaf(e, w.z, acc.z); acc.w = fmaf(e, w.w, acc.w);
        }
        z += fmaxf(acc.x, 0.f) * sw2[kc]   + fmaxf(acc.y, 0.f) * sw2[kc+1]
           + fmaxf(acc.z, 0.f) * sw2[kc+2] + fmaxf(acc.w, 0.f) * sw2[kc+3];
    }
    float sp = (z > 15.f) ? z : log1pf(__expf(z));
    g_spair[o * 128 + tid] = sp;
}

// ---------- GRU: 128 blocks x 128 threads, one thread per pair ----------
__global__ void __launch_bounds__(128) gru_kernel(
    const float* __restrict__ seqs, const int* __restrict__ lengths,
    const float* __restrict__ Wih, const float* __restrict__ bih,
    const float* __restrict__ Whh, const float* __restrict__ bhh,
    const float* __restrict__ Ws,  const float* __restrict__ bs)
{
    extern __shared__ __align__(16) float sm[];
    float* sWhh = sm;             // 12288
    float* sWih = sm + 12288;     // 3072
    float* sbR  = sm + 15360;     // 64
    float* sbZ  = sm + 15424;     // 64
    float* sbNX = sm + 15488;     // 64
    float* sbNH = sm + 15552;     // 64
    float* sWs  = sm + 15616;     // 64  -> 15680 floats = 62720 B

    int tid = threadIdx.x;
    for (int i = tid; i < 12288; i += 128) sWhh[i] = Whh[i];
    for (int i = tid; i < 3072;  i += 128) sWih[i] = Wih[i];
    if (tid < 64) {
        sbR[tid]  = bih[tid]       + bhh[tid];
        sbZ[tid]  = bih[64 + tid]  + bhh[64 + tid];
        sbNX[tid] = bih[128 + tid];
        sbNH[tid] = bhh[128 + tid];
        sWs[tid]  = Ws[tid];
    }
    __syncthreads();

    int p = blockIdx.x * 128 + tid;
    int len = lengths[p];
    int tmax = len;
    #pragma unroll
    for (int off = 16; off; off >>= 1)
        tmax = max(tmax, __shfl_xor_sync(0xffffffffu, tmax, off));

    const float4* xp = (const float4*)(seqs + (size_t)p * 2048);

    float h[64];
    #pragma unroll
    for (int k = 0; k < 64; ++k) h[k] = 0.f;

    float x[16], xn_[16];
    #pragma unroll
    for (int q = 0; q < 4; ++q) {
        float4 v = xp[q];
        x[4*q] = v.x; x[4*q+1] = v.y; x[4*q+2] = v.z; x[4*q+3] = v.w;
    }
    float2 nzb[64];   // (n, z) buffer; dynamic chunk index -> local mem (L1-backed)

    #pragma unroll 1
    for (int t = 0; t < tmax; ++t) {
        int tn = (t + 1 < 128) ? (t + 1) : t;      // prefetch next x
        #pragma unroll
        for (int q = 0; q < 4; ++q) {
            float4 v = xp[tn * 4 + q];
            xn_[4*q] = v.x; xn_[4*q+1] = v.y; xn_[4*q+2] = v.z; xn_[4*q+3] = v.w;
        }

        #pragma unroll 1
        for (int c = 0; c < 8; ++c) {              // 8 hidden units per chunk
            ull ar[4]  = {0,0,0,0};
            ull az[4]  = {0,0,0,0};
            ull anx[4] = {0,0,0,0};
            ull anh[4] = {0,0,0,0};

            const float* wbase = sWih + c * 8;
            #pragma unroll
            for (int f = 0; f < 16; ++f) {
                ull x2 = pk2(x[f]);
                ACC3(wbase + f * 192, x2, ar, az, anx);
            }
            const float* hbase = sWhh + c * 8;
            #pragma unroll
            for (int k = 0; k < 64; ++k) {
                ull h2 = pk2(h[k]);
                ACC3(hbase + k * 192, h2, ar, az, anh);
            }

            int j0 = c * 8;
            #pragma unroll
            for (int u = 0; u < 4; ++u) {
                float2 vr = upk(ar[u]), vz = upk(az[u]);
                float2 vx = upk(anx[u]), vh = upk(anh[u]);
                int j = j0 + 2 * u;
                float r0  = sigf(vr.x + sbR[j]);
                float zg0 = sigf(vz.x + sbZ[j]);
                float n0  = tanhe(vx.x + sbNX[j] + r0 * (vh.x + sbNH[j]));
                nzb[j] = make_float2(n0, zg0);
                float r1  = sigf(vr.y + sbR[j + 1]);
                float zg1 = sigf(vz.y + sbZ[j + 1]);
                float n1  = tanhe(vx.y + sbNX[j + 1] + r1 * (vh.y + sbNH[j + 1]));
                nzb[j + 1] = make_float2(n1, zg1);
            }
        }

        bool keep = (t < len);
        #pragma unroll
        for (int k = 0; k < 64; ++k) {
            float2 nz = nzb[k];
            float hn = nz.x + nz.y * (h[k] - nz.x);   // (1-z)*n + z*h
            h[k] = keep ? hn : h[k];
        }
        #pragma unroll
        for (int q = 0; q < 16; ++q) x[q] = xn_[q];
    }

    // epilogue: p_seq = sigmoid(h.Ws + bs); contribution = s_pair * p_seq
    float acc = bs[0];
    #pragma unroll
    for (int k = 0; k < 64; ++k) acc = fmaf(h[k], sWs[k], acc);
    float val = g_spair[p] * sigf(acc);

    __syncthreads();               // done with weights; reuse smem for reduction
    sm[tid] = val;
    __syncthreads();
    #pragma unroll 1
    for (int s = 64; s > 0; s >>= 1) {
        if (tid < s) sm[tid] += sm[tid + s];
        __syncthreads();
    }
    if (tid == 0) g_part[blockIdx.x] = sm[0];
}

// ---------- final deterministic reduction ----------
__global__ void final_kernel(float* __restrict__ out)
{
    __shared__ float red[128];
    int tid = threadIdx.x;
    red[tid] = g_part[tid];
    __syncthreads();
    #pragma unroll 1
    for (int s = 64; s > 0; s >>= 1) {
        if (tid < s) red[tid] += red[tid + s];
        __syncthreads();
    }
    if (tid == 0) out[0] = red[0];
}

// ---------- launch ----------
extern "C" void kernel_launch(void* const* d_in, const int* in_sizes, int n_in,
                              void* d_out, int out_size)
{
    const float* Of   = (const float*)d_in[0];
    const float* Df   = (const float*)d_in[1];
    const float* seqs = (const float*)d_in[2];
    const int*   lengths = (const int*)d_in[3];
    const float* WO1 = (const float*)d_in[4];  const float* bO1 = (const float*)d_in[5];
    const float* WO2 = (const float*)d_in[6];  const float* bO2 = (const float*)d_in[7];
    const float* WO3 = (const float*)d_in[8];  const float* bO3 = (const float*)d_in[9];
    const float* WD1 = (const float*)d_in[10]; const float* bD1 = (const float*)d_in[11];
    const float* WD2 = (const float*)d_in[12]; const float* bD2 = (const float*)d_in[13];
    const float* WD3 = (const float*)d_in[14]; const float* bD3 = (const float*)d_in[15];
    const float* Wp1 = (const float*)d_in[16]; const float* bp1 = (const float*)d_in[17];
    const float* Wp2 = (const float*)d_in[18]; const float* bp2 = (const float*)d_in[19];

    // GRU params: disambiguate dict order (W_ih,b_ih,W_hh,b_hh) vs
    // signature order (W_ih,W_hh,b_ih,b_hh) via element counts.
    const float *Wih, *bih, *Whh, *bhh;
    if (in_sizes[21] == 12288) {            // signature order
        Wih = (const float*)d_in[20]; Whh = (const float*)d_in[21];
        bih = (const float*)d_in[22]; bhh = (const float*)d_in[23];
    } else {                                // dict order
        Wih = (const float*)d_in[20]; bih = (const float*)d_in[21];
        Whh = (const float*)d_in[22]; bhh = (const float*)d_in[23];
    }
    const float* Ws = (const float*)d_in[24];
    const float* bs = (const float*)d_in[25];
    float* out = (float*)d_out;

    const int GRU_SMEM = 15680 * (int)sizeof(float);   // 62720 B > 48K default
    cudaFuncSetAttribute(gru_kernel, cudaFuncAttributeMaxDynamicSharedMemorySize, GRU_SMEM);

    enc_kernel<<<256, 128>>>(Of, Df, WO1, bO1, WO2, bO2, WO3, bO3,
                             WD1, bD1, WD2, bD2, WD3, bD3);
    pair_kernel<<<128, 128>>>(Wp1, bp1, Wp2, bp2);
    gru_kernel<<<128, 128, GRU_SMEM>>>(seqs, lengths, Wih, bih, Whh, bhh, Ws, bs);
    final_kernel<<<1, 128>>>(out);
}

// round 9
// speedup vs baseline: 3.8559x; 3.8559x over previous
#include <cuda_runtime.h>
#include <cuda_bf16.h>
#include <math.h>
#include <stdint.h>

// ---------------- device scratch (no allocations allowed) ----------------
__device__ float g_eo[128 * 64];
__device__ float g_ed[128 * 64];
__device__ float g_spair[16384];
__device__ float g_part[128];

// ---------------- math helpers ----------------
__device__ __forceinline__ float sigf(float v) {
    return __fdividef(1.0f, 1.0f + __expf(-v));
}
__device__ __forceinline__ float tanha(float x) {
    float y; asm("tanh.approx.f32 %0, %1;" : "=f"(y) : "f"(x)); return y;
}
__device__ __forceinline__ float sigt(float v) {       // sigmoid via hw tanh
    return fmaf(0.5f, tanha(0.5f * v), 0.5f);
}

// pack two f32 -> bf16x2 (lo = first elem, hi = second elem)
__device__ __forceinline__ uint32_t pack_bf2(float lo, float hi) {
    uint32_t r;
    asm("cvt.rn.bf16x2.f32 %0, %1, %2;" : "=r"(r) : "f"(hi), "f"(lo));
    return r;
}
__device__ __forceinline__ float bf_lo(uint32_t u) { return __uint_as_float(u << 16); }
__device__ __forceinline__ float bf_hi(uint32_t u) { return __uint_as_float(u & 0xFFFF0000u); }

__device__ __forceinline__ uint32_t smem_u32(const void* p) {
    uint32_t a;
    asm("{ .reg .u64 t; cvta.to.shared.u64 t, %1; cvt.u32.u64 %0, t; }" : "=r"(a) : "l"(p));
    return a;
}
__device__ __forceinline__ void ldsm4(uint32_t& r0, uint32_t& r1, uint32_t& r2, uint32_t& r3,
                                      uint32_t addr) {
    asm volatile("ldmatrix.sync.aligned.m8n8.x4.shared.b16 {%0,%1,%2,%3}, [%4];"
                 : "=r"(r0), "=r"(r1), "=r"(r2), "=r"(r3) : "r"(addr));
}
__device__ __forceinline__ void mma16816(float* c,
                                         uint32_t a0, uint32_t a1, uint32_t a2, uint32_t a3,
                                         uint32_t b0, uint32_t b1) {
    asm volatile("mma.sync.aligned.m16n8k16.row.col.f32.bf16.bf16.f32 "
                 "{%0,%1,%2,%3}, {%4,%5,%6,%7}, {%8,%9}, {%0,%1,%2,%3};"
                 : "+f"(c[0]), "+f"(c[1]), "+f"(c[2]), "+f"(c[3])
                 : "r"(a0), "r"(a1), "r"(a2), "r"(a3), "r"(b0), "r"(b1));
}

// ---------------- node encoders ----------------
__global__ void __launch_bounds__(128) enc_kernel(
    const float* __restrict__ Of, const float* __restrict__ Df,
    const float* __restrict__ WO1, const float* __restrict__ bO1,
    const float* __restrict__ WO2, const float* __restrict__ bO2,
    const float* __restrict__ WO3, const float* __restrict__ bO3,
    const float* __restrict__ WD1, const float* __restrict__ bD1,
    const float* __restrict__ WD2, const float* __restrict__ bD2,
    const float* __restrict__ WD3, const float* __restrict__ bD3)
{
    __shared__ float fs[64], h1[128], h2[128];
    int b = blockIdx.x;
    int row = b & 127;
    bool isD = (b >= 128);
    const float* feats = isD ? Df : Of;
    const float* W1 = isD ? WD1 : WO1; const float* b1 = isD ? bD1 : bO1;
    const float* W2 = isD ? WD2 : WO2; const float* b2 = isD ? bD2 : bO2;
    const float* W3 = isD ? WD3 : WO3; const float* b3 = isD ? bD3 : bO3;
    float* out = isD ? g_ed : g_eo;
    int tid = threadIdx.x;

    if (tid < 64) fs[tid] = feats[row * 64 + tid];
    __syncthreads();

    float a = b1[tid];
    #pragma unroll 8
    for (int i = 0; i < 64; ++i) a = fmaf(fs[i], W1[i * 128 + tid], a);
    h1[tid] = fmaxf(a, 0.f);
    __syncthreads();

    a = b2[tid];
    #pragma unroll 8
    for (int i = 0; i < 128; ++i) a = fmaf(h1[i], W2[i * 128 + tid], a);
    h2[tid] = fmaxf(a, 0.f);
    __syncthreads();

    if (tid < 64) {
        a = b3[tid];
        #pragma unroll 8
        for (int i = 0; i < 128; ++i) a = fmaf(h2[i], W3[i * 64 + tid], a);
        out[row * 64 + tid] = a;
    }
}

// ---------------- pair head ----------------
__global__ void __launch_bounds__(128) pair_kernel(
    const float* __restrict__ Wp1, const float* __restrict__ bp1,
    const float* __restrict__ Wp2, const float* __restrict__ bp2)
{
    __shared__ float ao[128], sb[128], sw2[128], seo[64];
    int tid = threadIdx.x, o = blockIdx.x;
    sb[tid] = bp1[tid];
    sw2[tid] = Wp2[tid];
    if (tid < 64) seo[tid] = g_eo[o * 64 + tid];
    __syncthreads();

    float a = 0.f;
    #pragma unroll 8
    for (int i = 0; i < 64; ++i) a = fmaf(seo[i], Wp1[i * 128 + tid], a);
    ao[tid] = a;
    __syncthreads();

    float ed[64];
    const float4* edp = (const float4*)(g_ed + tid * 64);
    #pragma unroll
    for (int q = 0; q < 16; ++q) {
        float4 v = edp[q];
        ed[4*q] = v.x; ed[4*q+1] = v.y; ed[4*q+2] = v.z; ed[4*q+3] = v.w;
    }

    float z = bp2[0];
    #pragma unroll 1
    for (int kc = 0; kc < 128; kc += 4) {
        float4 acc = make_float4(ao[kc] + sb[kc], ao[kc+1] + sb[kc+1],
                                 ao[kc+2] + sb[kc+2], ao[kc+3] + sb[kc+3]);
        #pragma unroll
        for (int i = 0; i < 64; ++i) {
            float e = ed[i];
            float4 w = *(const float4*)&Wp1[(64 + i) * 128 + kc];
            acc.x = fmaf(e, w.x, acc.x); acc.y = fmaf(e, w.y, acc.y);
            acc.z = fmaf(e, w.z, acc.z); acc.w = fmaf(e, w.w, acc.w);
        }
        z += fmaxf(acc.x, 0.f) * sw2[kc]   + fmaxf(acc.y, 0.f) * sw2[kc+1]
           + fmaxf(acc.z, 0.f) * sw2[kc+2] + fmaxf(acc.w, 0.f) * sw2[kc+3];
    }
    float sp = (z > 15.f) ? z : log1pf(__expf(z));
    g_spair[o * 128 + tid] = sp;
}

// ---------------- GRU on mma.sync bf16 (hi/lo split) ----------------
// CTA: 256 threads = 8 warps; warp w owns rows [16w, 16w+16) of 128 pairs.
// SMEM weights: B[n][k] bf16, n = gate*64+j (r,z,n), padded row strides to kill
// ldmatrix bank conflicts. h stays in registers: C-frag of ntile pair (2k,2k+1)
// IS the A-frag of k-tile k, so only cvt packs between steps.
#define WHH_HI 0
#define WHH_LO 27648
#define WIH_HI 55296
#define WIH_LO 64512
#define BOFF   73728            // br[64] bz[64] bnx[64] bnh[64] Ws[64]
#define REDOFF 75008
#define GRU_SMEM 75072

#define CSEL_X(nt) ((nt) < 8 ? Cr[(nt)] : ((nt) < 16 ? Cz[(nt)-8] : Cn1[(nt)-16]))
#define CSEL_H(nt) ((nt) < 8 ? Cr[(nt)] : ((nt) < 16 ? Cz[(nt)-8] : Cn2[(nt)-16]))

__global__ void __launch_bounds__(256, 1) gru_mma_kernel(
    const float* __restrict__ seqs, const int* __restrict__ lengths,
    const float* __restrict__ Wih, const float* __restrict__ bih,
    const float* __restrict__ Whh, const float* __restrict__ bhh,
    const float* __restrict__ Ws,  const float* __restrict__ bs)
{
    extern __shared__ __align__(16) char smc[];
    uint32_t smb = smem_u32(smc);
    int tid = threadIdx.x;
    int w = tid >> 5, lane = tid & 31;
    int tig = lane & 3, g = lane >> 2;

    // ---- stage weights (bf16 hi/lo split) ----
    for (int idx = tid; idx < 192 * 64; idx += 256) {
        int n = idx >> 6, k = idx & 63;
        float wv = Whh[k * 192 + n];
        __nv_bfloat16 hb = __float2bfloat16(wv);
        __nv_bfloat16 lb = __float2bfloat16(wv - __bfloat162float(hb));
        *(unsigned short*)(smc + WHH_HI + n * 144 + k * 2) = __bfloat16_as_ushort(hb);
        *(unsigned short*)(smc + WHH_LO + n * 144 + k * 2) = __bfloat16_as_ushort(lb);
    }
    for (int idx = tid; idx < 192 * 16; idx += 256) {
        int n = idx >> 4, k = idx & 15;
        float wv = Wih[k * 192 + n];
        __nv_bfloat16 hb = __float2bfloat16(wv);
        __nv_bfloat16 lb = __float2bfloat16(wv - __bfloat162float(hb));
        *(unsigned short*)(smc + WIH_HI + n * 48 + k * 2) = __bfloat16_as_ushort(hb);
        *(unsigned short*)(smc + WIH_LO + n * 48 + k * 2) = __bfloat16_as_ushort(lb);
    }
    float* sbr  = (float*)(smc + BOFF);
    float* sbz  = sbr + 64;
    float* sbnx = sbr + 128;
    float* sbnh = sbr + 192;
    float* sWs  = sbr + 256;
    if (tid < 64) {
        sbr[tid]  = bih[tid]       + bhh[tid];
        sbz[tid]  = bih[64 + tid]  + bhh[64 + tid];
        sbnx[tid] = bih[128 + tid];
        sbnh[tid] = bhh[128 + tid];
        sWs[tid]  = Ws[tid];
    }
    __syncthreads();

    // ---- per-thread geometry ----
    int r0 = 16 * w + g;
    int p0 = blockIdx.x * 128 + r0;
    int p1 = p0 + 8;
    int l0 = lengths[p0], l1 = lengths[p1];
    int tmax = max(l0, l1);
    #pragma unroll
    for (int o = 16; o; o >>= 1) tmax = max(tmax, __shfl_xor_sync(0xffffffffu, tmax, o));

    // ldmatrix lane bases
    int rl = (lane & 7) + ((lane >> 4) << 3);
    int chunk = (lane >> 3) & 1;
    uint32_t aHHh = smb + WHH_HI + (uint32_t)rl * 144u + (uint32_t)chunk * 16u;
    uint32_t aHHl = smb + WHH_LO + (uint32_t)rl * 144u + (uint32_t)chunk * 16u;
    uint32_t aIHh = smb + WIH_HI + (uint32_t)rl * 48u  + (uint32_t)chunk * 16u;
    uint32_t aIHl = smb + WIH_LO + (uint32_t)rl * 48u  + (uint32_t)chunk * 16u;

    const float* xb0 = seqs + (size_t)p0 * 2048 + 2 * tig;
    const float* xb1 = seqs + (size_t)p1 * 2048 + 2 * tig;

    // ---- state ----
    float hreg[8][4];
    #pragma unroll
    for (int n = 0; n < 8; ++n)
        #pragma unroll
        for (int i = 0; i < 4; ++i) hreg[n][i] = 0.f;

    uint32_t ahh[4][4], ahl[4][4];
    #pragma unroll
    for (int kt = 0; kt < 4; ++kt)
        #pragma unroll
        for (int i = 0; i < 4; ++i) { ahh[kt][i] = 0u; ahl[kt][i] = 0u; }

    float xf[8];
    {
        float2 f0 = *(const float2*)(xb0);
        float2 f1 = *(const float2*)(xb1);
        float2 f2 = *(const float2*)(xb0 + 8);
        float2 f3 = *(const float2*)(xb1 + 8);
        xf[0]=f0.x; xf[1]=f0.y; xf[2]=f1.x; xf[3]=f1.y;
        xf[4]=f2.x; xf[5]=f2.y; xf[6]=f3.x; xf[7]=f3.y;
    }

    #pragma unroll 1
    for (int t = 0; t < tmax; ++t) {
        // x A-fragments (hi/lo)
        uint32_t axh[4], axl[4];
        #pragma unroll
        for (int i = 0; i < 4; ++i) {
            axh[i] = pack_bf2(xf[2*i], xf[2*i+1]);
            axl[i] = pack_bf2(xf[2*i]   - bf_lo(axh[i]),
                              xf[2*i+1] - bf_hi(axh[i]));
        }

        // accumulators
        float Cr[8][4], Cz[8][4], Cn1[8][4], Cn2[8][4];
        #pragma unroll
        for (int n = 0; n < 8; ++n)
            #pragma unroll
            for (int i = 0; i < 4; ++i) { Cr[n][i]=0.f; Cz[n][i]=0.f; Cn1[n][i]=0.f; Cn2[n][i]=0.f; }

        // ---- gx: K=16 ----
        #pragma unroll
        for (int np = 0; np < 12; ++np) {
            uint32_t b0,b1,b2,b3, q0,q1,q2,q3;
            ldsm4(b0,b1,b2,b3, aIHh + (uint32_t)np * 768u);
            ldsm4(q0,q1,q2,q3, aIHl + (uint32_t)np * 768u);
            float* c0 = CSEL_X(2*np);
            float* c1 = CSEL_X(2*np + 1);
            mma16816(c0, axh[0],axh[1],axh[2],axh[3], b0,b1);
            mma16816(c1, axh[0],axh[1],axh[2],axh[3], b2,b3);
            mma16816(c0, axl[0],axl[1],axl[2],axl[3], b0,b1);
            mma16816(c1, axl[0],axl[1],axl[2],axl[3], b2,b3);
            mma16816(c0, axh[0],axh[1],axh[2],axh[3], q0,q1);
            mma16816(c1, axh[0],axh[1],axh[2],axh[3], q2,q3);
        }

        // prefetch x(t+1)
        int tn = (t + 1 < 128) ? t + 1 : 127;
        float xn[8];
        {
            float2 f0 = *(const float2*)(xb0 + tn * 16);
            float2 f1 = *(const float2*)(xb1 + tn * 16);
            float2 f2 = *(const float2*)(xb0 + tn * 16 + 8);
            float2 f3 = *(const float2*)(xb1 + tn * 16 + 8);
            xn[0]=f0.x; xn[1]=f0.y; xn[2]=f1.x; xn[3]=f1.y;
            xn[4]=f2.x; xn[5]=f2.y; xn[6]=f3.x; xn[7]=f3.y;
        }

        // ---- gh: K=64 ----
        #pragma unroll
        for (int np = 0; np < 12; ++np) {
            float* c0 = CSEL_H(2*np);
            float* c1 = CSEL_H(2*np + 1);
            #pragma unroll
            for (int kt = 0; kt < 4; ++kt) {
                uint32_t b0,b1,b2,b3, q0,q1,q2,q3;
                ldsm4(b0,b1,b2,b3, aHHh + (uint32_t)np * 2304u + (uint32_t)kt * 32u);
                ldsm4(q0,q1,q2,q3, aHHl + (uint32_t)np * 2304u + (uint32_t)kt * 32u);
                mma16816(c0, ahh[kt][0],ahh[kt][1],ahh[kt][2],ahh[kt][3], b0,b1);
                mma16816(c1, ahh[kt][0],ahh[kt][1],ahh[kt][2],ahh[kt][3], b2,b3);
                mma16816(c0, ahl[kt][0],ahl[kt][1],ahl[kt][2],ahl[kt][3], b0,b1);
                mma16816(c1, ahl[kt][0],ahl[kt][1],ahl[kt][2],ahl[kt][3], b2,b3);
                mma16816(c0, ahh[kt][0],ahh[kt][1],ahh[kt][2],ahh[kt][3], q0,q1);
                mma16816(c1, ahh[kt][0],ahh[kt][1],ahh[kt][2],ahh[kt][3], q2,q3);
            }
        }

        // ---- gates + h update ----
        bool k0 = (t < l0), k1 = (t < l1);
        #pragma unroll
        for (int nt = 0; nt < 8; ++nt) {
            float2 bR  = *(const float2*)&sbr [8*nt + 2*tig];
            float2 bZ  = *(const float2*)&sbz [8*nt + 2*tig];
            float2 bNX = *(const float2*)&sbnx[8*nt + 2*tig];
            float2 bNH = *(const float2*)&sbnh[8*nt + 2*tig];
            #pragma unroll
            for (int i = 0; i < 4; ++i) {
                float bRv  = (i & 1) ? bR.y  : bR.x;
                float bZv  = (i & 1) ? bZ.y  : bZ.x;
                float bNXv = (i & 1) ? bNX.y : bNX.x;
                float bNHv = (i & 1) ? bNH.y : bNH.x;
                float r  = sigt(Cr[nt][i] + bRv);
                float zg = sigt(Cz[nt][i] + bZv);
                float n  = tanha(Cn1[nt][i] + bNXv + r * (Cn2[nt][i] + bNHv));
                float hn = n + zg * (hreg[nt][i] - n);
                bool keep = (i < 2) ? k0 : k1;
                hreg[nt][i] = keep ? hn : hreg[nt][i];
            }
        }

        // ---- repack h into A-fragments (hi/lo) for next step ----
        #pragma unroll
        for (int kt = 0; kt < 4; ++kt) {
            int n0 = 2*kt, n1 = n0 + 1;
            uint32_t u0 = pack_bf2(hreg[n0][0], hreg[n0][1]);
            uint32_t u1 = pack_bf2(hreg[n0][2], hreg[n0][3]);
            uint32_t u2 = pack_bf2(hreg[n1][0], hreg[n1][1]);
            uint32_t u3 = pack_bf2(hreg[n1][2], hreg[n1][3]);
            ahh[kt][0] = u0; ahh[kt][1] = u1; ahh[kt][2] = u2; ahh[kt][3] = u3;
            ahl[kt][0] = pack_bf2(hreg[n0][0] - bf_lo(u0), hreg[n0][1] - bf_hi(u0));
            ahl[kt][1] = pack_bf2(hreg[n0][2] - bf_lo(u1), hreg[n0][3] - bf_hi(u1));
            ahl[kt][2] = pack_bf2(hreg[n1][0] - bf_lo(u2), hreg[n1][1] - bf_hi(u2));
            ahl[kt][3] = pack_bf2(hreg[n1][2] - bf_lo(u3), hreg[n1][3] - bf_hi(u3));
        }

        #pragma unroll
        for (int i = 0; i < 8; ++i) xf[i] = xn[i];
    }

    // ---- epilogue: p_seq = sigmoid(h.Ws + bs); contribution = s_pair * p_seq ----
    float dot0 = 0.f, dot1 = 0.f;
    #pragma unroll
    for (int nt = 0; nt < 8; ++nt) {
        float2 wsp = *(const float2*)&sWs[8*nt + 2*tig];
        dot0 += hreg[nt][0] * wsp.x + hreg[nt][1] * wsp.y;
        dot1 += hreg[nt][2] * wsp.x + hreg[nt][3] * wsp.y;
    }
    dot0 += __shfl_xor_sync(0xffffffffu, dot0, 1);
    dot0 += __shfl_xor_sync(0xffffffffu, dot0, 2);
    dot1 += __shfl_xor_sync(0xffffffffu, dot1, 1);
    dot1 += __shfl_xor_sync(0xffffffffu, dot1, 2);

    float bsv = bs[0];
    float val = 0.f;
    if (tig == 0) {
        val  = g_spair[p0] * sigf(dot0 + bsv);
        val += g_spair[p1] * sigf(dot1 + bsv);
    }
    #pragma unroll
    for (int o = 16; o; o >>= 1) val += __shfl_xor_sync(0xffffffffu, val, o);

    float* sred = (float*)(smc + REDOFF);
    if (lane == 0) sred[w] = val;
    __syncthreads();
    if (tid == 0) {
        float s = 0.f;
        #pragma unroll
        for (int i = 0; i < 8; ++i) s += sred[i];
        g_part[blockIdx.x] = s;
    }
}

// ---------------- final deterministic reduction ----------------
__global__ void final_kernel(float* __restrict__ out)
{
    __shared__ float red[128];
    int tid = threadIdx.x;
    red[tid] = g_part[tid];
    __syncthreads();
    #pragma unroll 1
    for (int s = 64; s > 0; s >>= 1) {
        if (tid < s) red[tid] += red[tid + s];
        __syncthreads();
    }
    if (tid == 0) out[0] = red[0];
}

// ---------------- launch ----------------
extern "C" void kernel_launch(void* const* d_in, const int* in_sizes, int n_in,
                              void* d_out, int out_size)
{
    const float* Of   = (const float*)d_in[0];
    const float* Df   = (const float*)d_in[1];
    const float* seqs = (const float*)d_in[2];
    const int*   lengths = (const int*)d_in[3];
    const float* WO1 = (const float*)d_in[4];  const float* bO1 = (const float*)d_in[5];
    const float* WO2 = (const float*)d_in[6];  const float* bO2 = (const float*)d_in[7];
    const float* WO3 = (const float*)d_in[8];  const float* bO3 = (const float*)d_in[9];
    const float* WD1 = (const float*)d_in[10]; const float* bD1 = (const float*)d_in[11];
    const float* WD2 = (const float*)d_in[12]; const float* bD2 = (const float*)d_in[13];
    const float* WD3 = (const float*)d_in[14]; const float* bD3 = (const float*)d_in[15];
    const float* Wp1 = (const float*)d_in[16]; const float* bp1 = (const float*)d_in[17];
    const float* Wp2 = (const float*)d_in[18]; const float* bp2 = (const float*)d_in[19];

    const float *Wih, *bih, *Whh, *bhh;
    if (in_sizes[21] == 12288) {            // signature order: W_ih, W_hh, b_ih, b_hh
        Wih = (const float*)d_in[20]; Whh = (const float*)d_in[21];
        bih = (const float*)d_in[22]; bhh = (const float*)d_in[23];
    } else {                                // dict order: W_ih, b_ih, W_hh, b_hh
        Wih = (const float*)d_in[20]; bih = (const float*)d_in[21];
        Whh = (const float*)d_in[22]; bhh = (const float*)d_in[23];
    }
    const float* Ws = (const float*)d_in[24];
    const float* bs = (const float*)d_in[25];
    float* out = (float*)d_out;

    cudaFuncSetAttribute(gru_mma_kernel, cudaFuncAttributeMaxDynamicSharedMemorySize, GRU_SMEM);

    enc_kernel<<<256, 128>>>(Of, Df, WO1, bO1, WO2, bO2, WO3, bO3,
                             WD1, bD1, WD2, bD2, WD3, bD3);
    pair_kernel<<<128, 128>>>(Wp1, bp1, Wp2, bp2);
    gru_mma_kernel<<<128, 256, GRU_SMEM>>>(seqs, lengths, Wih, bih, Whh, bhh, Ws, bs);
    final_kernel<<<1, 128>>>(out);
}

// round 12
// speedup vs baseline: 4.9500x; 1.2838x over previous
#include <cuda_runtime.h>
#include <cuda_bf16.h>
#include <cuda_fp16.h>
#include <math.h>
#include <stdint.h>

// ---------------- device scratch (no allocations allowed) ----------------
__device__ float g_eo[128 * 64];
__device__ float g_ed[128 * 64];
__device__ float g_spair[16384];
__device__ float g_part[128];

// ---------------- math helpers ----------------
__device__ __forceinline__ float sigf(float v) {
    return __fdividef(1.0f, 1.0f + __expf(-v));
}
__device__ __forceinline__ float tanha(float x) {
    float y; asm("tanh.approx.f32 %0, %1;" : "=f"(y) : "f"(x)); return y;
}
__device__ __forceinline__ float sigt(float v) {       // sigmoid via hw tanh
    return fmaf(0.5f, tanha(0.5f * v), 0.5f);
}

// pack two f32 -> f16x2 (lo halfword = first arg, hi halfword = second arg)
__device__ __forceinline__ uint32_t pack_h2(float lo, float hi) {
    uint32_t r;
    asm("cvt.rn.f16x2.f32 %0, %1, %2;" : "=r"(r) : "f"(hi), "f"(lo));
    return r;
}
__device__ __forceinline__ float h2_lo(uint32_t u) {
    return __half2float(__ushort_as_half((unsigned short)(u & 0xFFFFu)));
}
__device__ __forceinline__ float h2_hi(uint32_t u) {
    return __half2float(__ushort_as_half((unsigned short)(u >> 16)));
}

__device__ __forceinline__ uint32_t smem_u32(const void* p) {
    uint32_t a;
    asm("{ .reg .u64 t; cvta.to.shared.u64 t, %1; cvt.u32.u64 %0, t; }" : "=r"(a) : "l"(p));
    return a;
}
__device__ __forceinline__ void ldsm4(uint32_t& r0, uint32_t& r1, uint32_t& r2, uint32_t& r3,
                                      uint32_t addr) {
    asm volatile("ldmatrix.sync.aligned.m8n8.x4.shared.b16 {%0,%1,%2,%3}, [%4];"
                 : "=r"(r0), "=r"(r1), "=r"(r2), "=r"(r3) : "r"(addr));
}
__device__ __forceinline__ void mma16816(float* c,
                                         uint32_t a0, uint32_t a1, uint32_t a2, uint32_t a3,
                                         uint32_t b0, uint32_t b1) {
    asm volatile("mma.sync.aligned.m16n8k16.row.col.f32.f16.f16.f32 "
                 "{%0,%1,%2,%3}, {%4,%5,%6,%7}, {%8,%9}, {%0,%1,%2,%3};"
                 : "+f"(c[0]), "+f"(c[1]), "+f"(c[2]), "+f"(c[3])
                 : "r"(a0), "r"(a1), "r"(a2), "r"(a3), "r"(b0), "r"(b1));
}

// ---------------- node encoders ----------------
__global__ void __launch_bounds__(128) enc_kernel(
    const float* __restrict__ Of, const float* __restrict__ Df,
    const float* __restrict__ WO1, const float* __restrict__ bO1,
    const float* __restrict__ WO2, const float* __restrict__ bO2,
    const float* __restrict__ WO3, const float* __restrict__ bO3,
    const float* __restrict__ WD1, const float* __restrict__ bD1,
    const float* __restrict__ WD2, const float* __restrict__ bD2,
    const float* __restrict__ WD3, const float* __restrict__ bD3)
{
    __shared__ float fs[64], h1[128], h2[128];
    int b = blockIdx.x;
    int row = b & 127;
    bool isD = (b >= 128);
    const float* feats = isD ? Df : Of;
    const float* W1 = isD ? WD1 : WO1; const float* b1 = isD ? bD1 : bO1;
    const float* W2 = isD ? WD2 : WO2; const float* b2 = isD ? bD2 : bO2;
    const float* W3 = isD ? WD3 : WO3; const float* b3 = isD ? bD3 : bO3;
    float* out = isD ? g_ed : g_eo;
    int tid = threadIdx.x;

    if (tid < 64) fs[tid] = feats[row * 64 + tid];
    __syncthreads();

    float a = b1[tid];
    #pragma unroll 8
    for (int i = 0; i < 64; ++i) a = fmaf(fs[i], W1[i * 128 + tid], a);
    h1[tid] = fmaxf(a, 0.f);
    __syncthreads();

    a = b2[tid];
    #pragma unroll 8
    for (int i = 0; i < 128; ++i) a = fmaf(h1[i], W2[i * 128 + tid], a);
    h2[tid] = fmaxf(a, 0.f);
    __syncthreads();

    if (tid < 64) {
        a = b3[tid];
        #pragma unroll 8
        for (int i = 0; i < 128; ++i) a = fmaf(h2[i], W3[i * 64 + tid], a);
        out[row * 64 + tid] = a;
    }
}

// ---------------- pair head ----------------
__global__ void __launch_bounds__(128) pair_kernel(
    const float* __restrict__ Wp1, const float* __restrict__ bp1,
    const float* __restrict__ Wp2, const float* __restrict__ bp2)
{
    __shared__ float ao[128], sb[128], sw2[128], seo[64];
    int tid = threadIdx.x, o = blockIdx.x;
    sb[tid] = bp1[tid];
    sw2[tid] = Wp2[tid];
    if (tid < 64) seo[tid] = g_eo[o * 64 + tid];
    __syncthreads();

    float a = 0.f;
    #pragma unroll 8
    for (int i = 0; i < 64; ++i) a = fmaf(seo[i], Wp1[i * 128 + tid], a);
    ao[tid] = a;
    __syncthreads();

    float ed[64];
    const float4* edp = (const float4*)(g_ed + tid * 64);
    #pragma unroll
    for (int q = 0; q < 16; ++q) {
        float4 v = edp[q];
        ed[4*q] = v.x; ed[4*q+1] = v.y; ed[4*q+2] = v.z; ed[4*q+3] = v.w;
    }

    float z = bp2[0];
    #pragma unroll 1
    for (int kc = 0; kc < 128; kc += 4) {
        float4 acc = make_float4(ao[kc] + sb[kc], ao[kc+1] + sb[kc+1],
                                 ao[kc+2] + sb[kc+2], ao[kc+3] + sb[kc+3]);
        #pragma unroll
        for (int i = 0; i < 64; ++i) {
            float e = ed[i];
            float4 w = *(const float4*)&Wp1[(64 + i) * 128 + kc];
            acc.x = fmaf(e, w.x, acc.x); acc.y = fmaf(e, w.y, acc.y);
            acc.z = fmaf(e, w.z, acc.z); acc.w = fmaf(e, w.w, acc.w);
        }
        z += fmaxf(acc.x, 0.f) * sw2[kc]   + fmaxf(acc.y, 0.f) * sw2[kc+1]
           + fmaxf(acc.z, 0.f) * sw2[kc+2] + fmaxf(acc.w, 0.f) * sw2[kc+3];
    }
    float sp = (z > 15.f) ? z : log1pf(__expf(z));
    g_spair[o * 128 + tid] = sp;
}

// ---------------- GRU on mma.sync fp16 (A hi/lo split, B single fp16) -------
// CTA: 256 threads = 8 warps; warp w owns rows [16w, 16w+16) of 128 pairs.
// SMEM weights: B[n][k] fp16 (n = gate*64+j for r,z,n), row strides 144/48 B
// (conflict-free for ldmatrix). h stays in registers: C-frag of n-tile pair
// (2k,2k+1) IS the A-frag of k-tile k, so only cvt packs between steps.
// n-tile-pair np covers 16 n-rows -> ldmatrix stride per np is 16*rowstride:
// 16*144 = 2304 (W_hh), 16*48 = 768 (W_ih).   [R10/R11 halved these: bug]
#define WHH_OFF 0
#define WIH_OFF 27648
#define BOFF    36864            // br[64] bz[64] bnx[64] bnh[64] Ws[64]
#define REDOFF  38144
#define GRU_SMEM 38208

#define CSEL_X(nt) ((nt) < 8 ? Cr[(nt)] : ((nt) < 16 ? Cz[(nt)-8] : Cn1[(nt)-16]))
#define CSEL_H(nt) ((nt) < 8 ? Cr[(nt)] : ((nt) < 16 ? Cz[(nt)-8] : Cn2[(nt)-16]))

__global__ void __launch_bounds__(256, 1) gru_mma_kernel(
    const float* __restrict__ seqs, const int* __restrict__ lengths,
    const float* __restrict__ Wih, const float* __restrict__ bih,
    const float* __restrict__ Whh, const float* __restrict__ bhh,
    const float* __restrict__ Ws,  const float* __restrict__ bs)
{
    extern __shared__ __align__(16) char smc[];
    uint32_t smb = smem_u32(smc);
    int tid = threadIdx.x;
    int w = tid >> 5, lane = tid & 31;
    int tig = lane & 3, g = lane >> 2;

    // ---- stage weights (single fp16) ----
    for (int idx = tid; idx < 192 * 64; idx += 256) {
        int n = idx >> 6, k = idx & 63;
        float wv = Whh[k * 192 + n];
        *(unsigned short*)(smc + WHH_OFF + n * 144 + k * 2) =
            __half_as_ushort(__float2half_rn(wv));
    }
    for (int idx = tid; idx < 192 * 16; idx += 256) {
        int n = idx >> 4, k = idx & 15;
        float wv = Wih[k * 192 + n];
        *(unsigned short*)(smc + WIH_OFF + n * 48 + k * 2) =
            __half_as_ushort(__float2half_rn(wv));
    }
    float* sbr  = (float*)(smc + BOFF);
    float* sbz  = sbr + 64;
    float* sbnx = sbr + 128;
    float* sbnh = sbr + 192;
    float* sWs  = sbr + 256;
    if (tid < 64) {
        sbr[tid]  = bih[tid]       + bhh[tid];
        sbz[tid]  = bih[64 + tid]  + bhh[64 + tid];
        sbnx[tid] = bih[128 + tid];
        sbnh[tid] = bhh[128 + tid];
        sWs[tid]  = Ws[tid];
    }
    __syncthreads();

    // ---- per-thread geometry ----
    int r0 = 16 * w + g;
    int p0 = blockIdx.x * 128 + r0;
    int p1 = p0 + 8;
    int l0 = lengths[p0], l1 = lengths[p1];
    int tmax = max(l0, l1);
    #pragma unroll
    for (int o = 16; o; o >>= 1) tmax = max(tmax, __shfl_xor_sync(0xffffffffu, tmax, o));

    // ldmatrix lane bases
    int rl = (lane & 7) + ((lane >> 4) << 3);
    int chunk = (lane >> 3) & 1;
    uint32_t aHH = smb + WHH_OFF + (uint32_t)rl * 144u + (uint32_t)chunk * 16u;
    uint32_t aIH = smb + WIH_OFF + (uint32_t)rl * 48u  + (uint32_t)chunk * 16u;

    const float* xb0 = seqs + (size_t)p0 * 2048 + 2 * tig;
    const float* xb1 = seqs + (size_t)p1 * 2048 + 2 * tig;

    // ---- state ----
    float hreg[8][4];
    #pragma unroll
    for (int n = 0; n < 8; ++n)
        #pragma unroll
        for (int i = 0; i < 4; ++i) hreg[n][i] = 0.f;

    uint32_t ahh[4][4], ahl[4][4];
    #pragma unroll
    for (int kt = 0; kt < 4; ++kt)
        #pragma unroll
        for (int i = 0; i < 4; ++i) { ahh[kt][i] = 0u; ahl[kt][i] = 0u; }

    float xf[8];
    {
        float2 f0 = *(const float2*)(xb0);
        float2 f1 = *(const float2*)(xb1);
        float2 f2 = *(const float2*)(xb0 + 8);
        float2 f3 = *(const float2*)(xb1 + 8);
        xf[0]=f0.x; xf[1]=f0.y; xf[2]=f1.x; xf[3]=f1.y;
        xf[4]=f2.x; xf[5]=f2.y; xf[6]=f3.x; xf[7]=f3.y;
    }

    #pragma unroll 1
    for (int t = 0; t < tmax; ++t) {
        // x A-fragments (hi/lo fp16 split)
        uint32_t axh[4], axl[4];
        #pragma unroll
        for (int i = 0; i < 4; ++i) {
            axh[i] = pack_h2(xf[2*i], xf[2*i+1]);
            axl[i] = pack_h2(xf[2*i]   - h2_lo(axh[i]),
                             xf[2*i+1] - h2_hi(axh[i]));
        }

        // accumulators
        float Cr[8][4], Cz[8][4], Cn1[8][4], Cn2[8][4];
        #pragma unroll
        for (int n = 0; n < 8; ++n)
            #pragma unroll
            for (int i = 0; i < 4; ++i) { Cr[n][i]=0.f; Cz[n][i]=0.f; Cn1[n][i]=0.f; Cn2[n][i]=0.f; }

        // ---- gx: K=16 ----
        #pragma unroll
        for (int np = 0; np < 12; ++np) {
            uint32_t b0,b1,b2,b3;
            ldsm4(b0,b1,b2,b3, aIH + (uint32_t)np * 768u);
            float* c0 = CSEL_X(2*np);
            float* c1 = CSEL_X(2*np + 1);
            mma16816(c0, axh[0],axh[1],axh[2],axh[3], b0,b1);
            mma16816(c1, axh[0],axh[1],axh[2],axh[3], b2,b3);
            mma16816(c0, axl[0],axl[1],axl[2],axl[3], b0,b1);
            mma16816(c1, axl[0],axl[1],axl[2],axl[3], b2,b3);
        }

        // prefetch x(t+1)
        int tn = (t + 1 < 128) ? t + 1 : 127;
        float xn[8];
        {
            float2 f0 = *(const float2*)(xb0 + tn * 16);
            float2 f1 = *(const float2*)(xb1 + tn * 16);
            float2 f2 = *(const float2*)(xb0 + tn * 16 + 8);
            float2 f3 = *(const float2*)(xb1 + tn * 16 + 8);
            xn[0]=f0.x; xn[1]=f0.y; xn[2]=f1.x; xn[3]=f1.y;
            xn[4]=f2.x; xn[5]=f2.y; xn[6]=f3.x; xn[7]=f3.y;
        }

        // ---- gh: K=64 ----
        #pragma unroll
        for (int np = 0; np < 12; ++np) {
            float* c0 = CSEL_H(2*np);
            float* c1 = CSEL_H(2*np + 1);
            #pragma unroll
            for (int kt = 0; kt < 4; ++kt) {
                uint32_t b0,b1,b2,b3;
                ldsm4(b0,b1,b2,b3, aHH + (uint32_t)np * 2304u + (uint32_t)kt * 32u);
                mma16816(c0, ahh[kt][0],ahh[kt][1],ahh[kt][2],ahh[kt][3], b0,b1);
                mma16816(c1, ahh[kt][0],ahh[kt][1],ahh[kt][2],ahh[kt][3], b2,b3);
                mma16816(c0, ahl[kt][0],ahl[kt][1],ahl[kt][2],ahl[kt][3], b0,b1);
                mma16816(c1, ahl[kt][0],ahl[kt][1],ahl[kt][2],ahl[kt][3], b2,b3);
            }
        }

        // ---- gates + h update ----
        bool k0 = (t < l0), k1 = (t < l1);
        #pragma unroll
        for (int nt = 0; nt < 8; ++nt) {
            float2 bR  = *(const float2*)&sbr [8*nt + 2*tig];
            float2 bZ  = *(const float2*)&sbz [8*nt + 2*tig];
            float2 bNX = *(const float2*)&sbnx[8*nt + 2*tig];
            float2 bNH = *(const float2*)&sbnh[8*nt + 2*tig];
            #pragma unroll
            for (int i = 0; i < 4; ++i) {
                float bRv  = (i & 1) ? bR.y  : bR.x;
                float bZv  = (i & 1) ? bZ.y  : bZ.x;
                float bNXv = (i & 1) ? bNX.y : bNX.x;
                float bNHv = (i & 1) ? bNH.y : bNH.x;
                float r  = sigt(Cr[nt][i] + bRv);
                float zg = sigt(Cz[nt][i] + bZv);
                float n  = tanha(Cn1[nt][i] + bNXv + r * (Cn2[nt][i] + bNHv));
                float hn = n + zg * (hreg[nt][i] - n);
                bool keep = (i < 2) ? k0 : k1;
                hreg[nt][i] = keep ? hn : hreg[nt][i];
            }
        }

        // ---- repack h into fp16 hi/lo A-fragments for next step ----
        #pragma unroll
        for (int kt = 0; kt < 4; ++kt) {
            int n0 = 2*kt, n1 = n0 + 1;
            uint32_t u0 = pack_h2(hreg[n0][0], hreg[n0][1]);
            uint32_t u1 = pack_h2(hreg[n0][2], hreg[n0][3]);
            uint32_t u2 = pack_h2(hreg[n1][0], hreg[n1][1]);
            uint32_t u3 = pack_h2(hreg[n1][2], hreg[n1][3]);
            ahh[kt][0] = u0; ahh[kt][1] = u1; ahh[kt][2] = u2; ahh[kt][3] = u3;
            ahl[kt][0] = pack_h2(hreg[n0][0] - h2_lo(u0), hreg[n0][1] - h2_hi(u0));
            ahl[kt][1] = pack_h2(hreg[n0][2] - h2_lo(u1), hreg[n0][3] - h2_hi(u1));
            ahl[kt][2] = pack_h2(hreg[n1][0] - h2_lo(u2), hreg[n1][1] - h2_hi(u2));
            ahl[kt][3] = pack_h2(hreg[n1][2] - h2_lo(u3), hreg[n1][3] - h2_hi(u3));
        }

        #pragma unroll
        for (int i = 0; i < 8; ++i) xf[i] = xn[i];
    }

    // ---- epilogue: p_seq = sigmoid(h.Ws + bs); contribution = s_pair * p_seq ----
    float dot0 = 0.f, dot1 = 0.f;
    #pragma unroll
    for (int nt = 0; nt < 8; ++nt) {
        float2 wsp = *(const float2*)&sWs[8*nt + 2*tig];
        dot0 += hreg[nt][0] * wsp.x + hreg[nt][1] * wsp.y;
        dot1 += hreg[nt][2] * wsp.x + hreg[nt][3] * wsp.y;
    }
    dot0 += __shfl_xor_sync(0xffffffffu, dot0, 1);
    dot0 += __shfl_xor_sync(0xffffffffu, dot0, 2);
    dot1 += __shfl_xor_sync(0xffffffffu, dot1, 1);
    dot1 += __shfl_xor_sync(0xffffffffu, dot1, 2);

    float bsv = bs[0];
    float val = 0.f;
    if (tig == 0) {
        val  = g_spair[p0] * sigf(dot0 + bsv);
        val += g_spair[p1] * sigf(dot1 + bsv);
    }
    #pragma unroll
    for (int o = 16; o; o >>= 1) val += __shfl_xor_sync(0xffffffffu, val, o);

    float* sred = (float*)(smc + REDOFF);
    if (lane == 0) sred[w] = val;
    __syncthreads();
    if (tid == 0) {
        float s = 0.f;
        #pragma unroll
        for (int i = 0; i < 8; ++i) s += sred[i];
        g_part[blockIdx.x] = s;
    }
}

// ---------------- final deterministic reduction ----------------
__global__ void final_kernel(float* __restrict__ out)
{
    __shared__ float red[128];
    int tid = threadIdx.x;
    red[tid] = g_part[tid];
    __syncthreads();
    #pragma unroll 1
    for (int s = 64; s > 0; s >>= 1) {
        if (tid < s) red[tid] += red[tid + s];
        __syncthreads();
    }
    if (tid == 0) out[0] = red[0];
}

// ---------------- launch ----------------
extern "C" void kernel_launch(void* const* d_in, const int* in_sizes, int n_in,
                              void* d_out, int out_size)
{
    const float* Of   = (const float*)d_in[0];
    const float* Df   = (const float*)d_in[1];
    const float* seqs = (const float*)d_in[2];
    const int*   lengths = (const int*)d_in[3];
    const float* WO1 = (const float*)d_in[4];  const float* bO1 = (const float*)d_in[5];
    const float* WO2 = (const float*)d_in[6];  const float* bO2 = (const float*)d_in[7];
    const float* WO3 = (const float*)d_in[8];  const float* bO3 = (const float*)d_in[9];
    const float* WD1 = (const float*)d_in[10]; const float* bD1 = (const float*)d_in[11];
    const float* WD2 = (const float*)d_in[12]; const float* bD2 = (const float*)d_in[13];
    const float* WD3 = (const float*)d_in[14]; const float* bD3 = (const float*)d_in[15];
    const float* Wp1 = (const float*)d_in[16]; const float* bp1 = (const float*)d_in[17];
    const float* Wp2 = (const float*)d_in[18]; const float* bp2 = (const float*)d_in[19];

    const float *Wih, *bih, *Whh, *bhh;
    if (in_sizes[21] == 12288) {            // signature order: W_ih, W_hh, b_ih, b_hh
        Wih = (const float*)d_in[20]; Whh = (const float*)d_in[21];
        bih = (const float*)d_in[22]; bhh = (const float*)d_in[23];
    } else {                                // dict order: W_ih, b_ih, W_hh, b_hh
        Wih = (const float*)d_in[20]; bih = (const float*)d_in[21];
        Whh = (const float*)d_in[22]; bhh = (const float*)d_in[23];
    }
    const float* Ws = (const float*)d_in[24];
    const float* bs = (const float*)d_in[25];
    float* out = (float*)d_out;

    cudaFuncSetAttribute(gru_mma_kernel, cudaFuncAttributeMaxDynamicSharedMemorySize, GRU_SMEM);

    enc_kernel<<<256, 128>>>(Of, Df, WO1, bO1, WO2, bO2, WO3, bO3,
                             WD1, bD1, WD2, bD2, WD3, bD3);
    pair_kernel<<<128, 128>>>(Wp1, bp1, Wp2, bp2);
    gru_mma_kernel<<<128, 256, GRU_SMEM>>>(seqs, lengths, Wih, bih, Whh, bhh, Ws, bs);
    final_kernel<<<1, 128>>>(out);
}

// round 13
// speedup vs baseline: 7.3265x; 1.4801x over previous
#include <cuda_runtime.h>
#include <cuda_bf16.h>
#include <cuda_fp16.h>
#include <math.h>
#include <stdint.h>

// ---------------- device scratch (no allocations allowed) ----------------
__device__ float g_eo[128 * 64];
__device__ float g_ed[128 * 64];
__device__ float g_spair[16384];
__device__ float g_part[128];
__device__ int   g_perm[16384];
__device__ int   g_chunkhist[128][128];   // [chunk][key]
__device__ int   g_chunkpre[128][128];    // exclusive prefix over chunks per key
__device__ int   g_binbase[128];          // exclusive prefix over keys

// ---------------- math helpers ----------------
__device__ __forceinline__ float sigf(float v) {
    return __fdividef(1.0f, 1.0f + __expf(-v));
}
__device__ __forceinline__ float tanha(float x) {
    float y; asm("tanh.approx.f32 %0, %1;" : "=f"(y) : "f"(x)); return y;
}
__device__ __forceinline__ float sigt(float v) {       // sigmoid via hw tanh
    return fmaf(0.5f, tanha(0.5f * v), 0.5f);
}

// pack two f32 -> f16x2 (lo halfword = first arg, hi halfword = second arg)
__device__ __forceinline__ uint32_t pack_h2(float lo, float hi) {
    uint32_t r;
    asm("cvt.rn.f16x2.f32 %0, %1, %2;" : "=r"(r) : "f"(hi), "f"(lo));
    return r;
}
__device__ __forceinline__ float h2_lo(uint32_t u) {
    return __half2float(__ushort_as_half((unsigned short)(u & 0xFFFFu)));
}
__device__ __forceinline__ float h2_hi(uint32_t u) {
    return __half2float(__ushort_as_half((unsigned short)(u >> 16)));
}

__device__ __forceinline__ uint32_t smem_u32(const void* p) {
    uint32_t a;
    asm("{ .reg .u64 t; cvta.to.shared.u64 t, %1; cvt.u32.u64 %0, t; }" : "=r"(a) : "l"(p));
    return a;
}
__device__ __forceinline__ void ldsm4(uint32_t& r0, uint32_t& r1, uint32_t& r2, uint32_t& r3,
                                      uint32_t addr) {
    asm volatile("ldmatrix.sync.aligned.m8n8.x4.shared.b16 {%0,%1,%2,%3}, [%4];"
                 : "=r"(r0), "=r"(r1), "=r"(r2), "=r"(r3) : "r"(addr));
}
__device__ __forceinline__ void mma16816(float* c,
                                         uint32_t a0, uint32_t a1, uint32_t a2, uint32_t a3,
                                         uint32_t b0, uint32_t b1) {
    asm volatile("mma.sync.aligned.m16n8k16.row.col.f32.f16.f16.f32 "
                 "{%0,%1,%2,%3}, {%4,%5,%6,%7}, {%8,%9}, {%0,%1,%2,%3};"
                 : "+f"(c[0]), "+f"(c[1]), "+f"(c[2]), "+f"(c[3])
                 : "r"(a0), "r"(a1), "r"(a2), "r"(a3), "r"(b0), "r"(b1));
}

// ---------------- deterministic counting sort of pairs by length ----------------
// key = lengths[p] - 1  (lengths in [1,128])
__global__ void __launch_bounds__(128) sortA_hist(const int* __restrict__ lengths)
{
    __shared__ int sh[128];
    int c = blockIdx.x, i = threadIdx.x;
    sh[i] = 0;
    __syncthreads();
    atomicAdd(&sh[lengths[c * 128 + i] - 1], 1);
    __syncthreads();
    g_chunkhist[c][i] = sh[i];
}

__global__ void __launch_bounds__(128) sortB_scan()
{
    __shared__ int tot[128];
    int k = threadIdx.x;
    int run = 0;
    for (int c = 0; c < 128; ++c) {
        g_chunkpre[c][k] = run;
        run += g_chunkhist[c][k];
    }
    tot[k] = run;
    __syncthreads();
    if (k == 0) {
        int acc = 0;
        for (int q = 0; q < 128; ++q) { g_binbase[q] = acc; acc += tot[q]; }
    }
}

__global__ void __launch_bounds__(128) sortC_scatter(const int* __restrict__ lengths)
{
    __shared__ int keys[128];
    int c = blockIdx.x, i = threadIdx.x;
    int k = lengths[c * 128 + i] - 1;
    keys[i] = k;
    __syncthreads();
    int cnt = 0;
    for (int j = 0; j < i; ++j) cnt += (keys[j] == k);
    g_perm[g_binbase[k] + g_chunkpre[c][k] + cnt] = c * 128 + i;
}

// ---------------- node encoders ----------------
__global__ void __launch_bounds__(128) enc_kernel(
    const float* __restrict__ Of, const float* __restrict__ Df,
    const float* __restrict__ WO1, const float* __restrict__ bO1,
    const float* __restrict__ WO2, const float* __restrict__ bO2,
    const float* __restrict__ WO3, const float* __restrict__ bO3,
    const float* __restrict__ WD1, const float* __restrict__ bD1,
    const float* __restrict__ WD2, const float* __restrict__ bD2,
    const float* __restrict__ WD3, const float* __restrict__ bD3)
{
    __shared__ float fs[64], h1[128], h2[128];
    int b = blockIdx.x;
    int row = b & 127;
    bool isD = (b >= 128);
    const float* feats = isD ? Df : Of;
    const float* W1 = isD ? WD1 : WO1; const float* b1 = isD ? bD1 : bO1;
    const float* W2 = isD ? WD2 : WO2; const float* b2 = isD ? bD2 : bO2;
    const float* W3 = isD ? WD3 : WO3; const float* b3 = isD ? bD3 : bO3;
    float* out = isD ? g_ed : g_eo;
    int tid = threadIdx.x;

    if (tid < 64) fs[tid] = feats[row * 64 + tid];
    __syncthreads();

    float a = b1[tid];
    #pragma unroll 8
    for (int i = 0; i < 64; ++i) a = fmaf(fs[i], W1[i * 128 + tid], a);
    h1[tid] = fmaxf(a, 0.f);
    __syncthreads();

    a = b2[tid];
    #pragma unroll 8
    for (int i = 0; i < 128; ++i) a = fmaf(h1[i], W2[i * 128 + tid], a);
    h2[tid] = fmaxf(a, 0.f);
    __syncthreads();

    if (tid < 64) {
        a = b3[tid];
        #pragma unroll 8
        for (int i = 0; i < 128; ++i) a = fmaf(h2[i], W3[i * 64 + tid], a);
        out[row * 64 + tid] = a;
    }
}

// ---------------- pair head ----------------
__global__ void __launch_bounds__(128) pair_kernel(
    const float* __restrict__ Wp1, const float* __restrict__ bp1,
    const float* __restrict__ Wp2, const float* __restrict__ bp2)
{
    __shared__ float ao[128], sb[128], sw2[128], seo[64];
    int tid = threadIdx.x, o = blockIdx.x;
    sb[tid] = bp1[tid];
    sw2[tid] = Wp2[tid];
    if (tid < 64) seo[tid] = g_eo[o * 64 + tid];
    __syncthreads();

    float a = 0.f;
    #pragma unroll 8
    for (int i = 0; i < 64; ++i) a = fmaf(seo[i], Wp1[i * 128 + tid], a);
    ao[tid] = a;
    __syncthreads();

    float ed[64];
    const float4* edp = (const float4*)(g_ed + tid * 64);
    #pragma unroll
    for (int q = 0; q < 16; ++q) {
        float4 v = edp[q];
        ed[4*q] = v.x; ed[4*q+1] = v.y; ed[4*q+2] = v.z; ed[4*q+3] = v.w;
    }

    float z = bp2[0];
    #pragma unroll 1
    for (int kc = 0; kc < 128; kc += 4) {
        float4 acc = make_float4(ao[kc] + sb[kc], ao[kc+1] + sb[kc+1],
                                 ao[kc+2] + sb[kc+2], ao[kc+3] + sb[kc+3]);
        #pragma unroll
        for (int i = 0; i < 64; ++i) {
            float e = ed[i];
            float4 w = *(const float4*)&Wp1[(64 + i) * 128 + kc];
            acc.x = fmaf(e, w.x, acc.x); acc.y = fmaf(e, w.y, acc.y);
            acc.z = fmaf(e, w.z, acc.z); acc.w = fmaf(e, w.w, acc.w);
        }
        z += fmaxf(acc.x, 0.f) * sw2[kc]   + fmaxf(acc.y, 0.f) * sw2[kc+1]
           + fmaxf(acc.z, 0.f) * sw2[kc+2] + fmaxf(acc.w, 0.f) * sw2[kc+3];
    }
    float sp = (z > 15.f) ? z : log1pf(__expf(z));
    g_spair[o * 128 + tid] = sp;
}

// ---------------- GRU on mma.sync fp16 (A hi/lo split, B single fp16) -------
// CTA: 256 threads = 8 warps. Pairs are LENGTH-SORTED via g_perm; warp w<4
// takes ascending tile b*4+w, warp w>=4 takes descending tile 1023-(b*4+w-4),
// so each SMSP (w and w+4) serves ~(l_i + l_{1023-i}) ~ 131 warp-steps instead
// of ~252. Inside the t-loop everything is identical to R12.
#define WHH_OFF 0
#define WIH_OFF 27648
#define BOFF    36864            // br[64] bz[64] bnx[64] bnh[64] Ws[64]
#define REDOFF  38144
#define GRU_SMEM 38208

#define CSEL_X(nt) ((nt) < 8 ? Cr[(nt)] : ((nt) < 16 ? Cz[(nt)-8] : Cn1[(nt)-16]))
#define CSEL_H(nt) ((nt) < 8 ? Cr[(nt)] : ((nt) < 16 ? Cz[(nt)-8] : Cn2[(nt)-16]))

__global__ void __launch_bounds__(256, 1) gru_mma_kernel(
    const float* __restrict__ seqs, const int* __restrict__ lengths,
    const float* __restrict__ Wih, const float* __restrict__ bih,
    const float* __restrict__ Whh, const float* __restrict__ bhh,
    const float* __restrict__ Ws,  const float* __restrict__ bs)
{
    extern __shared__ __align__(16) char smc[];
    uint32_t smb = smem_u32(smc);
    int tid = threadIdx.x;
    int w = tid >> 5, lane = tid & 31;
    int tig = lane & 3, g = lane >> 2;

    // ---- stage weights (single fp16) ----
    for (int idx = tid; idx < 192 * 64; idx += 256) {
        int n = idx >> 6, k = idx & 63;
        float wv = Whh[k * 192 + n];
        *(unsigned short*)(smc + WHH_OFF + n * 144 + k * 2) =
            __half_as_ushort(__float2half_rn(wv));
    }
    for (int idx = tid; idx < 192 * 16; idx += 256) {
        int n = idx >> 4, k = idx & 15;
        float wv = Wih[k * 192 + n];
        *(unsigned short*)(smc + WIH_OFF + n * 48 + k * 2) =
            __half_as_ushort(__float2half_rn(wv));
    }
    float* sbr  = (float*)(smc + BOFF);
    float* sbz  = sbr + 64;
    float* sbnx = sbr + 128;
    float* sbnh = sbr + 192;
    float* sWs  = sbr + 256;
    if (tid < 64) {
        sbr[tid]  = bih[tid]       + bhh[tid];
        sbz[tid]  = bih[64 + tid]  + bhh[64 + tid];
        sbnx[tid] = bih[128 + tid];
        sbnh[tid] = bhh[128 + tid];
        sWs[tid]  = Ws[tid];
    }
    __syncthreads();

    // ---- per-thread geometry: length-sorted tile assignment ----
    int tileA = blockIdx.x * 4 + (w & 3);
    int tile  = (w < 4) ? tileA : (1023 - tileA);
    int base  = tile * 16;
    int p0 = g_perm[base + g];
    int p1 = g_perm[base + g + 8];
    int l0 = lengths[p0], l1 = lengths[p1];
    int tmax = max(l0, l1);
    #pragma unroll
    for (int o = 16; o; o >>= 1) tmax = max(tmax, __shfl_xor_sync(0xffffffffu, tmax, o));

    // ldmatrix lane bases
    int rl = (lane & 7) + ((lane >> 4) << 3);
    int chunk = (lane >> 3) & 1;
    uint32_t aHH = smb + WHH_OFF + (uint32_t)rl * 144u + (uint32_t)chunk * 16u;
    uint32_t aIH = smb + WIH_OFF + (uint32_t)rl * 48u  + (uint32_t)chunk * 16u;

    const float* xb0 = seqs + (size_t)p0 * 2048 + 2 * tig;
    const float* xb1 = seqs + (size_t)p1 * 2048 + 2 * tig;

    // ---- state ----
    float hreg[8][4];
    #pragma unroll
    for (int n = 0; n < 8; ++n)
        #pragma unroll
        for (int i = 0; i < 4; ++i) hreg[n][i] = 0.f;

    uint32_t ahh[4][4], ahl[4][4];
    #pragma unroll
    for (int kt = 0; kt < 4; ++kt)
        #pragma unroll
        for (int i = 0; i < 4; ++i) { ahh[kt][i] = 0u; ahl[kt][i] = 0u; }

    float xf[8];
    {
        float2 f0 = *(const float2*)(xb0);
        float2 f1 = *(const float2*)(xb1);
        float2 f2 = *(const float2*)(xb0 + 8);
        float2 f3 = *(const float2*)(xb1 + 8);
        xf[0]=f0.x; xf[1]=f0.y; xf[2]=f1.x; xf[3]=f1.y;
        xf[4]=f2.x; xf[5]=f2.y; xf[6]=f3.x; xf[7]=f3.y;
    }

    #pragma unroll 1
    for (int t = 0; t < tmax; ++t) {
        // x A-fragments (hi/lo fp16 split)
        uint32_t axh[4], axl[4];
        #pragma unroll
        for (int i = 0; i < 4; ++i) {
            axh[i] = pack_h2(xf[2*i], xf[2*i+1]);
            axl[i] = pack_h2(xf[2*i]   - h2_lo(axh[i]),
                             xf[2*i+1] - h2_hi(axh[i]));
        }

        // accumulators
        float Cr[8][4], Cz[8][4], Cn1[8][4], Cn2[8][4];
        #pragma unroll
        for (int n = 0; n < 8; ++n)
            #pragma unroll
            for (int i = 0; i < 4; ++i) { Cr[n][i]=0.f; Cz[n][i]=0.f; Cn1[n][i]=0.f; Cn2[n][i]=0.f; }

        // ---- gx: K=16 ----
        #pragma unroll
        for (int np = 0; np < 12; ++np) {
            uint32_t b0,b1,b2,b3;
            ldsm4(b0,b1,b2,b3, aIH + (uint32_t)np * 768u);
            float* c0 = CSEL_X(2*np);
            float* c1 = CSEL_X(2*np + 1);
            mma16816(c0, axh[0],axh[1],axh[2],axh[3], b0,b1);
            mma16816(c1, axh[0],axh[1],axh[2],axh[3], b2,b3);
            mma16816(c0, axl[0],axl[1],axl[2],axl[3], b0,b1);
            mma16816(c1, axl[0],axl[1],axl[2],axl[3], b2,b3);
        }

        // prefetch x(t+1)
        int tn = (t + 1 < 128) ? t + 1 : 127;
        float xn[8];
        {
            float2 f0 = *(const float2*)(xb0 + tn * 16);
            float2 f1 = *(const float2*)(xb1 + tn * 16);
            float2 f2 = *(const float2*)(xb0 + tn * 16 + 8);
            float2 f3 = *(const float2*)(xb1 + tn * 16 + 8);
            xn[0]=f0.x; xn[1]=f0.y; xn[2]=f1.x; xn[3]=f1.y;
            xn[4]=f2.x; xn[5]=f2.y; xn[6]=f3.x; xn[7]=f3.y;
        }

        // ---- gh: K=64 ----
        #pragma unroll
        for (int np = 0; np < 12; ++np) {
            float* c0 = CSEL_H(2*np);
            float* c1 = CSEL_H(2*np + 1);
            #pragma unroll
            for (int kt = 0; kt < 4; ++kt) {
                uint32_t b0,b1,b2,b3;
                ldsm4(b0,b1,b2,b3, aHH + (uint32_t)np * 2304u + (uint32_t)kt * 32u);
                mma16816(c0, ahh[kt][0],ahh[kt][1],ahh[kt][2],ahh[kt][3], b0,b1);
                mma16816(c1, ahh[kt][0],ahh[kt][1],ahh[kt][2],ahh[kt][3], b2,b3);
                mma16816(c0, ahl[kt][0],ahl[kt][1],ahl[kt][2],ahl[kt][3], b0,b1);
                mma16816(c1, ahl[kt][0],ahl[kt][1],ahl[kt][2],ahl[kt][3], b2,b3);
            }
        }

        // ---- gates + h update ----
        bool k0 = (t < l0), k1 = (t < l1);
        #pragma unroll
        for (int nt = 0; nt < 8; ++nt) {
            float2 bR  = *(const float2*)&sbr [8*nt + 2*tig];
            float2 bZ  = *(const float2*)&sbz [8*nt + 2*tig];
            float2 bNX = *(const float2*)&sbnx[8*nt + 2*tig];
            float2 bNH = *(const float2*)&sbnh[8*nt + 2*tig];
            #pragma unroll
            for (int i = 0; i < 4; ++i) {
                float bRv  = (i & 1) ? bR.y  : bR.x;
                float bZv  = (i & 1) ? bZ.y  : bZ.x;
                float bNXv = (i & 1) ? bNX.y : bNX.x;
                float bNHv = (i & 1) ? bNH.y : bNH.x;
                float r  = sigt(Cr[nt][i] + bRv);
                float zg = sigt(Cz[nt][i] + bZv);
                float n  = tanha(Cn1[nt][i] + bNXv + r * (Cn2[nt][i] + bNHv));
                float hn = n + zg * (hreg[nt][i] - n);
                bool keep = (i < 2) ? k0 : k1;
                hreg[nt][i] = keep ? hn : hreg[nt][i];
            }
        }

        // ---- repack h into fp16 hi/lo A-fragments for next step ----
        #pragma unroll
        for (int kt = 0; kt < 4; ++kt) {
            int n0 = 2*kt, n1 = n0 + 1;
            uint32_t u0 = pack_h2(hreg[n0][0], hreg[n0][1]);
            uint32_t u1 = pack_h2(hreg[n0][2], hreg[n0][3]);
            uint32_t u2 = pack_h2(hreg[n1][0], hreg[n1][1]);
            uint32_t u3 = pack_h2(hreg[n1][2], hreg[n1][3]);
            ahh[kt][0] = u0; ahh[kt][1] = u1; ahh[kt][2] = u2; ahh[kt][3] = u3;
            ahl[kt][0] = pack_h2(hreg[n0][0] - h2_lo(u0), hreg[n0][1] - h2_hi(u0));
            ahl[kt][1] = pack_h2(hreg[n0][2] - h2_lo(u1), hreg[n0][3] - h2_hi(u1));
            ahl[kt][2] = pack_h2(hreg[n1][0] - h2_lo(u2), hreg[n1][1] - h2_hi(u2));
            ahl[kt][3] = pack_h2(hreg[n1][2] - h2_lo(u3), hreg[n1][3] - h2_hi(u3));
        }

        #pragma unroll
        for (int i = 0; i < 8; ++i) xf[i] = xn[i];
    }

    // ---- epilogue: p_seq = sigmoid(h.Ws + bs); contribution = s_pair * p_seq ----
    float dot0 = 0.f, dot1 = 0.f;
    #pragma unroll
    for (int nt = 0; nt < 8; ++nt) {
        float2 wsp = *(const float2*)&sWs[8*nt + 2*tig];
        dot0 += hreg[nt][0] * wsp.x + hreg[nt][1] * wsp.y;
        dot1 += hreg[nt][2] * wsp.x + hreg[nt][3] * wsp.y;
    }
    dot0 += __shfl_xor_sync(0xffffffffu, dot0, 1);
    dot0 += __shfl_xor_sync(0xffffffffu, dot0, 2);
    dot1 += __shfl_xor_sync(0xffffffffu, dot1, 1);
    dot1 += __shfl_xor_sync(0xffffffffu, dot1, 2);

    float bsv = bs[0];
    float val = 0.f;
    if (tig == 0) {
        val  = g_spair[p0] * sigf(dot0 + bsv);
        val += g_spair[p1] * sigf(dot1 + bsv);
    }
    #pragma unroll
    for (int o = 16; o; o >>= 1) val += __shfl_xor_sync(0xffffffffu, val, o);

    float* sred = (float*)(smc + REDOFF);
    if (lane == 0) sred[w] = val;
    __syncthreads();
    if (tid == 0) {
        float s = 0.f;
        #pragma unroll
        for (int i = 0; i < 8; ++i) s += sred[i];
        g_part[blockIdx.x] = s;
    }
}

// ---------------- final deterministic reduction ----------------
__global__ void final_kernel(float* __restrict__ out)
{
    __shared__ float red[128];
    int tid = threadIdx.x;
    red[tid] = g_part[tid];
    __syncthreads();
    #pragma unroll 1
    for (int s = 64; s > 0; s >>= 1) {
        if (tid < s) red[tid] += red[tid + s];
        __syncthreads();
    }
    if (tid == 0) out[0] = red[0];
}

// ---------------- launch ----------------
extern "C" void kernel_launch(void* const* d_in, const int* in_sizes, int n_in,
                              void* d_out, int out_size)
{
    const float* Of   = (const float*)d_in[0];
    const float* Df   = (const float*)d_in[1];
    const float* seqs = (const float*)d_in[2];
    const int*   lengths = (const int*)d_in[3];
    const float* WO1 = (const float*)d_in[4];  const float* bO1 = (const float*)d_in[5];
    const float* WO2 = (const float*)d_in[6];  const float* bO2 = (const float*)d_in[7];
    const float* WO3 = (const float*)d_in[8];  const float* bO3 = (const float*)d_in[9];
    const float* WD1 = (const float*)d_in[10]; const float* bD1 = (const float*)d_in[11];
    const float* WD2 = (const float*)d_in[12]; const float* bD2 = (const float*)d_in[13];
    const float* WD3 = (const float*)d_in[14]; const float* bD3 = (const float*)d_in[15];
    const float* Wp1 = (const float*)d_in[16]; const float* bp1 = (const float*)d_in[17];
    const float* Wp2 = (const float*)d_in[18]; const float* bp2 = (const float*)d_in[19];

    const float *Wih, *bih, *Whh, *bhh;
    if (in_sizes[21] == 12288) {            // signature order: W_ih, W_hh, b_ih, b_hh
        Wih = (const float*)d_in[20]; Whh = (const float*)d_in[21];
        bih = (const float*)d_in[22]; bhh = (const float*)d_in[23];
    } else {                                // dict order: W_ih, b_ih, W_hh, b_hh
        Wih = (const float*)d_in[20]; bih = (const float*)d_in[21];
        Whh = (const float*)d_in[22]; bhh = (const float*)d_in[23];
    }
    const float* Ws = (const float*)d_in[24];
    const float* bs = (const float*)d_in[25];
    float* out = (float*)d_out;

    cudaFuncSetAttribute(gru_mma_kernel, cudaFuncAttributeMaxDynamicSharedMemorySize, GRU_SMEM);

    enc_kernel<<<256, 128>>>(Of, Df, WO1, bO1, WO2, bO2, WO3, bO3,
                             WD1, bD1, WD2, bD2, WD3, bD3);
    pair_kernel<<<128, 128>>>(Wp1, bp1, Wp2, bp2);
    sortA_hist<<<128, 128>>>(lengths);
    sortB_scan<<<1, 128>>>();
    sortC_scatter<<<128, 128>>>(lengths);
    gru_mma_kernel<<<128, 256, GRU_SMEM>>>(seqs, lengths, Wih, bih, Whh, bhh, Ws, bs);
    final_kernel<<<1, 128>>>(out);
}

// round 14
// speedup vs baseline: 7.7020x; 1.0512x over previous
#include <cuda_runtime.h>
#include <cuda_bf16.h>
#include <cuda_fp16.h>
#include <math.h>
#include <stdint.h>

// ---------------- device scratch (no allocations allowed) ----------------
__device__ float g_eo[128 * 64];
__device__ float g_ed[128 * 64];
__device__ float g_spair[16384];
__device__ float g_part[128];
__device__ int   g_perm[16384];
__device__ int   g_chunkhist[128][128];   // [key][chunk]  (transposed for sortB MLP)
__device__ int   g_chunkpre[128][128];    // [chunk][key]  exclusive prefix over chunks
__device__ int   g_binbase[128];          // exclusive prefix over keys

// ---------------- math helpers ----------------
__device__ __forceinline__ float sigf(float v) {
    return __fdividef(1.0f, 1.0f + __expf(-v));
}
__device__ __forceinline__ float tanha(float x) {
    float y; asm("tanh.approx.f32 %0, %1;" : "=f"(y) : "f"(x)); return y;
}
__device__ __forceinline__ float sigt(float v) {       // sigmoid via hw tanh
    return fmaf(0.5f, tanha(0.5f * v), 0.5f);
}

// pack two f32 -> f16x2 (lo halfword = first arg, hi halfword = second arg)
__device__ __forceinline__ uint32_t pack_h2(float lo, float hi) {
    uint32_t r;
    asm("cvt.rn.f16x2.f32 %0, %1, %2;" : "=r"(r) : "f"(hi), "f"(lo));
    return r;
}
__device__ __forceinline__ float h2_lo(uint32_t u) {
    return __half2float(__ushort_as_half((unsigned short)(u & 0xFFFFu)));
}
__device__ __forceinline__ float h2_hi(uint32_t u) {
    return __half2float(__ushort_as_half((unsigned short)(u >> 16)));
}

__device__ __forceinline__ uint32_t smem_u32(const void* p) {
    uint32_t a;
    asm("{ .reg .u64 t; cvta.to.shared.u64 t, %1; cvt.u32.u64 %0, t; }" : "=r"(a) : "l"(p));
    return a;
}
__device__ __forceinline__ void ldsm4(uint32_t& r0, uint32_t& r1, uint32_t& r2, uint32_t& r3,
                                      uint32_t addr) {
    asm volatile("ldmatrix.sync.aligned.m8n8.x4.shared.b16 {%0,%1,%2,%3}, [%4];"
                 : "=r"(r0), "=r"(r1), "=r"(r2), "=r"(r3) : "r"(addr));
}
__device__ __forceinline__ void mma16816(float* c,
                                         uint32_t a0, uint32_t a1, uint32_t a2, uint32_t a3,
                                         uint32_t b0, uint32_t b1) {
    asm volatile("mma.sync.aligned.m16n8k16.row.col.f32.f16.f16.f32 "
                 "{%0,%1,%2,%3}, {%4,%5,%6,%7}, {%8,%9}, {%0,%1,%2,%3};"
                 : "+f"(c[0]), "+f"(c[1]), "+f"(c[2]), "+f"(c[3])
                 : "r"(a0), "r"(a1), "r"(a2), "r"(a3), "r"(b0), "r"(b1));
}

// ---------------- deterministic counting sort of pairs by length ----------------
// key = lengths[p] - 1  (lengths in [1,128])
__global__ void __launch_bounds__(128) sortA_hist(const int* __restrict__ lengths)
{
    __shared__ int sh[128];
    int c = blockIdx.x, i = threadIdx.x;
    sh[i] = 0;
    __syncthreads();
    atomicAdd(&sh[lengths[c * 128 + i] - 1], 1);
    __syncthreads();
    g_chunkhist[i][c] = sh[i];          // transposed: [key][chunk]
}

__global__ void __launch_bounds__(128) sortB_scan()
{
    int k = threadIdx.x;
    // batch-load the whole row into registers (MLP ~32, one latency wave)
    int4 vals[32];
    const int4* row = (const int4*)&g_chunkhist[k][0];
    #pragma unroll
    for (int q = 0; q < 32; ++q) vals[q] = row[q];

    int run = 0;
    #pragma unroll
    for (int q = 0; q < 32; ++q) {
        int c = q * 4;
        g_chunkpre[c + 0][k] = run; run += vals[q].x;
        g_chunkpre[c + 1][k] = run; run += vals[q].y;
        g_chunkpre[c + 2][k] = run; run += vals[q].z;
        g_chunkpre[c + 3][k] = run; run += vals[q].w;
    }

    // exclusive scan over keys (Hillis-Steele, 7 steps)
    __shared__ int s[128];
    s[k] = run;
    __syncthreads();
    #pragma unroll
    for (int off = 1; off < 128; off <<= 1) {
        int t = (k >= off) ? s[k - off] : 0;
        __syncthreads();
        s[k] += t;
        __syncthreads();
    }
    g_binbase[k] = s[k] - run;          // inclusive -> exclusive
}

__global__ void __launch_bounds__(128) sortC_scatter(const int* __restrict__ lengths)
{
    __shared__ int keys[128];
    int c = blockIdx.x, i = threadIdx.x;
    int k = lengths[c * 128 + i] - 1;
    keys[i] = k;
    __syncthreads();
    int cnt = 0;
    for (int j = 0; j < i; ++j) cnt += (keys[j] == k);
    g_perm[g_binbase[k] + g_chunkpre[c][k] + cnt] = c * 128 + i;
}

// ---------------- node encoders ----------------
__global__ void __launch_bounds__(128) enc_kernel(
    const float* __restrict__ Of, const float* __restrict__ Df,
    const float* __restrict__ WO1, const float* __restrict__ bO1,
    const float* __restrict__ WO2, const float* __restrict__ bO2,
    const float* __restrict__ WO3, const float* __restrict__ bO3,
    const float* __restrict__ WD1, const float* __restrict__ bD1,
    const float* __restrict__ WD2, const float* __restrict__ bD2,
    const float* __restrict__ WD3, const float* __restrict__ bD3)
{
    __shared__ float fs[64], h1[128], h2[128];
    int b = blockIdx.x;
    int row = b & 127;
    bool isD = (b >= 128);
    const float* feats = isD ? Df : Of;
    const float* W1 = isD ? WD1 : WO1; const float* b1 = isD ? bD1 : bO1;
    const float* W2 = isD ? WD2 : WO2; const float* b2 = isD ? bD2 : bO2;
    const float* W3 = isD ? WD3 : WO3; const float* b3 = isD ? bD3 : bO3;
    float* out = isD ? g_ed : g_eo;
    int tid = threadIdx.x;

    if (tid < 64) fs[tid] = feats[row * 64 + tid];
    __syncthreads();

    float a = b1[tid];
    #pragma unroll 8
    for (int i = 0; i < 64; ++i) a = fmaf(fs[i], W1[i * 128 + tid], a);
    h1[tid] = fmaxf(a, 0.f);
    __syncthreads();

    a = b2[tid];
    #pragma unroll 8
    for (int i = 0; i < 128; ++i) a = fmaf(h1[i], W2[i * 128 + tid], a);
    h2[tid] = fmaxf(a, 0.f);
    __syncthreads();

    if (tid < 64) {
        a = b3[tid];
        #pragma unroll 8
        for (int i = 0; i < 128; ++i) a = fmaf(h2[i], W3[i * 64 + tid], a);
        out[row * 64 + tid] = a;
    }
}

// ---------------- pair head ----------------
__global__ void __launch_bounds__(128) pair_kernel(
    const float* __restrict__ Wp1, const float* __restrict__ bp1,
    const float* __restrict__ Wp2, const float* __restrict__ bp2)
{
    __shared__ float ao[128], sb[128], sw2[128], seo[64];
    int tid = threadIdx.x, o = blockIdx.x;
    sb[tid] = bp1[tid];
    sw2[tid] = Wp2[tid];
    if (tid < 64) seo[tid] = g_eo[o * 64 + tid];
    __syncthreads();

    float a = 0.f;
    #pragma unroll 8
    for (int i = 0; i < 64; ++i) a = fmaf(seo[i], Wp1[i * 128 + tid], a);
    ao[tid] = a;
    __syncthreads();

    float ed[64];
    const float4* edp = (const float4*)(g_ed + tid * 64);
    #pragma unroll
    for (int q = 0; q < 16; ++q) {
        float4 v = edp[q];
        ed[4*q] = v.x; ed[4*q+1] = v.y; ed[4*q+2] = v.z; ed[4*q+3] = v.w;
    }

    float z = bp2[0];
    #pragma unroll 1
    for (int kc = 0; kc < 128; kc += 4) {
        float4 acc = make_float4(ao[kc] + sb[kc], ao[kc+1] + sb[kc+1],
                                 ao[kc+2] + sb[kc+2], ao[kc+3] + sb[kc+3]);
        #pragma unroll
        for (int i = 0; i < 64; ++i) {
            float e = ed[i];
            float4 w = *(const float4*)&Wp1[(64 + i) * 128 + kc];
            acc.x = fmaf(e, w.x, acc.x); acc.y = fmaf(e, w.y, acc.y);
            acc.z = fmaf(e, w.z, acc.z); acc.w = fmaf(e, w.w, acc.w);
        }
        z += fmaxf(acc.x, 0.f) * sw2[kc]   + fmaxf(acc.y, 0.f) * sw2[kc+1]
           + fmaxf(acc.z, 0.f) * sw2[kc+2] + fmaxf(acc.w, 0.f) * sw2[kc+3];
    }
    float sp = (z > 15.f) ? z : log1pf(__expf(z));
    g_spair[o * 128 + tid] = sp;
}

// ---------------- GRU on mma.sync fp16 (A hi/lo split, B single fp16) -------
// CTA: 256 threads = 8 warps. Pairs are LENGTH-SORTED via g_perm; warp w<4
// takes ascending tile b*4+w, warp w>=4 takes descending tile 1023-(b*4+w-4),
// so each SMSP (w and w+4) serves ~(l_i + l_{1023-i}) ~ 131 warp-steps.
#define WHH_OFF 0
#define WIH_OFF 27648
#define BOFF    36864            // br[64] bz[64] bnx[64] bnh[64] Ws[64]
#define REDOFF  38144
#define GRU_SMEM 38208

#define CSEL_X(nt) ((nt) < 8 ? Cr[(nt)] : ((nt) < 16 ? Cz[(nt)-8] : Cn1[(nt)-16]))
#define CSEL_H(nt) ((nt) < 8 ? Cr[(nt)] : ((nt) < 16 ? Cz[(nt)-8] : Cn2[(nt)-16]))

__global__ void __launch_bounds__(256, 1) gru_mma_kernel(
    const float* __restrict__ seqs, const int* __restrict__ lengths,
    const float* __restrict__ Wih, const float* __restrict__ bih,
    const float* __restrict__ Whh, const float* __restrict__ bhh,
    const float* __restrict__ Ws,  const float* __restrict__ bs)
{
    extern __shared__ __align__(16) char smc[];
    uint32_t smb = smem_u32(smc);
    int tid = threadIdx.x;
    int w = tid >> 5, lane = tid & 31;
    int tig = lane & 3, g = lane >> 2;

    // ---- stage weights (single fp16) ----
    for (int idx = tid; idx < 192 * 64; idx += 256) {
        int n = idx >> 6, k = idx & 63;
        float wv = Whh[k * 192 + n];
        *(unsigned short*)(smc + WHH_OFF + n * 144 + k * 2) =
            __half_as_ushort(__float2half_rn(wv));
    }
    for (int idx = tid; idx < 192 * 16; idx += 256) {
        int n = idx >> 4, k = idx & 15;
        float wv = Wih[k * 192 + n];
        *(unsigned short*)(smc + WIH_OFF + n * 48 + k * 2) =
            __half_as_ushort(__float2half_rn(wv));
    }
    float* sbr  = (float*)(smc + BOFF);
    float* sbz  = sbr + 64;
    float* sbnx = sbr + 128;
    float* sbnh = sbr + 192;
    float* sWs  = sbr + 256;
    if (tid < 64) {
        sbr[tid]  = bih[tid]       + bhh[tid];
        sbz[tid]  = bih[64 + tid]  + bhh[64 + tid];
        sbnx[tid] = bih[128 + tid];
        sbnh[tid] = bhh[128 + tid];
        sWs[tid]  = Ws[tid];
    }
    __syncthreads();

    // ---- per-thread geometry: length-sorted tile assignment ----
    int tileA = blockIdx.x * 4 + (w & 3);
    int tile  = (w < 4) ? tileA : (1023 - tileA);
    int base  = tile * 16;
    int p0 = g_perm[base + g];
    int p1 = g_perm[base + g + 8];
    int l0 = lengths[p0], l1 = lengths[p1];
    int tmax = max(l0, l1);
    #pragma unroll
    for (int o = 16; o; o >>= 1) tmax = max(tmax, __shfl_xor_sync(0xffffffffu, tmax, o));

    // ldmatrix lane bases
    int rl = (lane & 7) + ((lane >> 4) << 3);
    int chunk = (lane >> 3) & 1;
    uint32_t aHH = smb + WHH_OFF + (uint32_t)rl * 144u + (uint32_t)chunk * 16u;
    uint32_t aIH = smb + WIH_OFF + (uint32_t)rl * 48u  + (uint32_t)chunk * 16u;

    const float* xb0 = seqs + (size_t)p0 * 2048 + 2 * tig;
    const float* xb1 = seqs + (size_t)p1 * 2048 + 2 * tig;

    // ---- state ----
    float hreg[8][4];
    #pragma unroll
    for (int n = 0; n < 8; ++n)
        #pragma unroll
        for (int i = 0; i < 4; ++i) hreg[n][i] = 0.f;

    uint32_t ahh[4][4], ahl[4][4];
    #pragma unroll
    for (int kt = 0; kt < 4; ++kt)
        #pragma unroll
        for (int i = 0; i < 4; ++i) { ahh[kt][i] = 0u; ahl[kt][i] = 0u; }

    float xf[8];
    {
        float2 f0 = *(const float2*)(xb0);
        float2 f1 = *(const float2*)(xb1);
        float2 f2 = *(const float2*)(xb0 + 8);
        float2 f3 = *(const float2*)(xb1 + 8);
        xf[0]=f0.x; xf[1]=f0.y; xf[2]=f1.x; xf[3]=f1.y;
        xf[4]=f2.x; xf[5]=f2.y; xf[6]=f3.x; xf[7]=f3.y;
    }

    #pragma unroll 1
    for (int t = 0; t < tmax; ++t) {
        // x A-fragments (hi/lo fp16 split)
        uint32_t axh[4], axl[4];
        #pragma unroll
        for (int i = 0; i < 4; ++i) {
            axh[i] = pack_h2(xf[2*i], xf[2*i+1]);
            axl[i] = pack_h2(xf[2*i]   - h2_lo(axh[i]),
                             xf[2*i+1] - h2_hi(axh[i]));
        }

        // accumulators
        float Cr[8][4], Cz[8][4], Cn1[8][4], Cn2[8][4];
        #pragma unroll
        for (int n = 0; n < 8; ++n)
            #pragma unroll
            for (int i = 0; i < 4; ++i) { Cr[n][i]=0.f; Cz[n][i]=0.f; Cn1[n][i]=0.f; Cn2[n][i]=0.f; }

        // ---- gx: K=16 ----
        #pragma unroll
        for (int np = 0; np < 12; ++np) {
            uint32_t b0,b1,b2,b3;
            ldsm4(b0,b1,b2,b3, aIH + (uint32_t)np * 768u);
            float* c0 = CSEL_X(2*np);
            float* c1 = CSEL_X(2*np + 1);
            mma16816(c0, axh[0],axh[1],axh[2],axh[3], b0,b1);
            mma16816(c1, axh[0],axh[1],axh[2],axh[3], b2,b3);
            mma16816(c0, axl[0],axl[1],axl[2],axl[3], b0,b1);
            mma16816(c1, axl[0],axl[1],axl[2],axl[3], b2,b3);
        }

        // prefetch x(t+1)
        int tn = (t + 1 < 128) ? t + 1 : 127;
        float xn[8];
        {
            float2 f0 = *(const float2*)(xb0 + tn * 16);
            float2 f1 = *(const float2*)(xb1 + tn * 16);
            float2 f2 = *(const float2*)(xb0 + tn * 16 + 8);
            float2 f3 = *(const float2*)(xb1 + tn * 16 + 8);
            xn[0]=f0.x; xn[1]=f0.y; xn[2]=f1.x; xn[3]=f1.y;
            xn[4]=f2.x; xn[5]=f2.y; xn[6]=f3.x; xn[7]=f3.y;
        }

        // ---- gh: K=64 ----
        #pragma unroll
        for (int np = 0; np < 12; ++np) {
            float* c0 = CSEL_H(2*np);
            float* c1 = CSEL_H(2*np + 1);
            #pragma unroll
            for (int kt = 0; kt < 4; ++kt) {
                uint32_t b0,b1,b2,b3;
                ldsm4(b0,b1,b2,b3, aHH + (uint32_t)np * 2304u + (uint32_t)kt * 32u);
                mma16816(c0, ahh[kt][0],ahh[kt][1],ahh[kt][2],ahh[kt][3], b0,b1);
                mma16816(c1, ahh[kt][0],ahh[kt][1],ahh[kt][2],ahh[kt][3], b2,b3);
                mma16816(c0, ahl[kt][0],ahl[kt][1],ahl[kt][2],ahl[kt][3], b0,b1);
                mma16816(c1, ahl[kt][0],ahl[kt][1],ahl[kt][2],ahl[kt][3], b2,b3);
            }
        }

        // ---- gates + h update ----
        bool k0 = (t < l0), k1 = (t < l1);
        #pragma unroll
        for (int nt = 0; nt < 8; ++nt) {
            float2 bR  = *(const float2*)&sbr [8*nt + 2*tig];
            float2 bZ  = *(const float2*)&sbz [8*nt + 2*tig];
            float2 bNX = *(const float2*)&sbnx[8*nt + 2*tig];
            float2 bNH = *(const float2*)&sbnh[8*nt + 2*tig];
            #pragma unroll
            for (int i = 0; i < 4; ++i) {
                float bRv  = (i & 1) ? bR.y  : bR.x;
                float bZv  = (i & 1) ? bZ.y  : bZ.x;
                float bNXv = (i & 1) ? bNX.y : bNX.x;
                float bNHv = (i & 1) ? bNH.y : bNH.x;
                float r  = sigt(Cr[nt][i] + bRv);
                float zg = sigt(Cz[nt][i] + bZv);
                float n  = tanha(Cn1[nt][i] + bNXv + r * (Cn2[nt][i] + bNHv));
                float hn = n + zg * (hreg[nt][i] - n);
                bool keep = (i < 2) ? k0 : k1;
                hreg[nt][i] = keep ? hn : hreg[nt][i];
            }
        }

        // ---- repack h into fp16 hi/lo A-fragments for next step ----
        #pragma unroll
        for (int kt = 0; kt < 4; ++kt) {
            int n0 = 2*kt, n1 = n0 + 1;
            uint32_t u0 = pack_h2(hreg[n0][0], hreg[n0][1]);
            uint32_t u1 = pack_h2(hreg[n0][2], hreg[n0][3]);
            uint32_t u2 = pack_h2(hreg[n1][0], hreg[n1][1]);
            uint32_t u3 = pack_h2(hreg[n1][2], hreg[n1][3]);
            ahh[kt][0] = u0; ahh[kt][1] = u1; ahh[kt][2] = u2; ahh[kt][3] = u3;
            ahl[kt][0] = pack_h2(hreg[n0][0] - h2_lo(u0), hreg[n0][1] - h2_hi(u0));
            ahl[kt][1] = pack_h2(hreg[n0][2] - h2_lo(u1), hreg[n0][3] - h2_hi(u1));
            ahl[kt][2] = pack_h2(hreg[n1][0] - h2_lo(u2), hreg[n1][1] - h2_hi(u2));
            ahl[kt][3] = pack_h2(hreg[n1][2] - h2_lo(u3), hreg[n1][3] - h2_hi(u3));
        }

        #pragma unroll
        for (int i = 0; i < 8; ++i) xf[i] = xn[i];
    }

    // ---- epilogue: p_seq = sigmoid(h.Ws + bs); contribution = s_pair * p_seq ----
    float dot0 = 0.f, dot1 = 0.f;
    #pragma unroll
    for (int nt = 0; nt < 8; ++nt) {
        float2 wsp = *(const float2*)&sWs[8*nt + 2*tig];
        dot0 += hreg[nt][0] * wsp.x + hreg[nt][1] * wsp.y;
        dot1 += hreg[nt][2] * wsp.x + hreg[nt][3] * wsp.y;
    }
    dot0 += __shfl_xor_sync(0xffffffffu, dot0, 1);
    dot0 += __shfl_xor_sync(0xffffffffu, dot0, 2);
    dot1 += __shfl_xor_sync(0xffffffffu, dot1, 1);
    dot1 += __shfl_xor_sync(0xffffffffu, dot1, 2);

    float bsv = bs[0];
    float val = 0.f;
    if (tig == 0) {
        val  = g_spair[p0] * sigf(dot0 + bsv);
        val += g_spair[p1] * sigf(dot1 + bsv);
    }
    #pragma unroll
    for (int o = 16; o; o >>= 1) val += __shfl_xor_sync(0xffffffffu, val, o);

    float* sred = (float*)(smc + REDOFF);
    if (lane == 0) sred[w] = val;
    __syncthreads();
    if (tid == 0) {
        float s = 0.f;
        #pragma unroll
        for (int i = 0; i < 8; ++i) s += sred[i];
        g_part[blockIdx.x] = s;
    }
}

// ---------------- final deterministic reduction ----------------
__global__ void final_kernel(float* __restrict__ out)
{
    __shared__ float red[128];
    int tid = threadIdx.x;
    red[tid] = g_part[tid];
    __syncthreads();
    #pragma unroll 1
    for (int s = 64; s > 0; s >>= 1) {
        if (tid < s) red[tid] += red[tid + s];
        __syncthreads();
    }
    if (tid == 0) out[0] = red[0];
}

// ---------------- launch ----------------
extern "C" void kernel_launch(void* const* d_in, const int* in_sizes, int n_in,
                              void* d_out, int out_size)
{
    const float* Of   = (const float*)d_in[0];
    const float* Df   = (const float*)d_in[1];
    const float* seqs = (const float*)d_in[2];
    const int*   lengths = (const int*)d_in[3];
    const float* WO1 = (const float*)d_in[4];  const float* bO1 = (const float*)d_in[5];
    const float* WO2 = (const float*)d_in[6];  const float* bO2 = (const float*)d_in[7];
    const float* WO3 = (const float*)d_in[8];  const float* bO3 = (const float*)d_in[9];
    const float* WD1 = (const float*)d_in[10]; const float* bD1 = (const float*)d_in[11];
    const float* WD2 = (const float*)d_in[12]; const float* bD2 = (const float*)d_in[13];
    const float* WD3 = (const float*)d_in[14]; const float* bD3 = (const float*)d_in[15];
    const float* Wp1 = (const float*)d_in[16]; const float* bp1 = (const float*)d_in[17];
    const float* Wp2 = (const float*)d_in[18]; const float* bp2 = (const float*)d_in[19];

    const float *Wih, *bih, *Whh, *bhh;
    if (in_sizes[21] == 12288) {            // signature order: W_ih, W_hh, b_ih, b_hh
        Wih = (const float*)d_in[20]; Whh = (const float*)d_in[21];
        bih = (const float*)d_in[22]; bhh = (const float*)d_in[23];
    } else {                                // dict order: W_ih, b_ih, W_hh, b_hh
        Wih = (const float*)d_in[20]; bih = (const float*)d_in[21];
        Whh = (const float*)d_in[22]; bhh = (const float*)d_in[23];
    }
    const float* Ws = (const float*)d_in[24];
    const float* bs = (const float*)d_in[25];
    float* out = (float*)d_out;

    cudaFuncSetAttribute(gru_mma_kernel, cudaFuncAttributeMaxDynamicSharedMemorySize, GRU_SMEM);

    enc_kernel<<<256, 128>>>(Of, Df, WO1, bO1, WO2, bO2, WO3, bO3,
                             WD1, bD1, WD2, bD2, WD3, bD3);
    pair_kernel<<<128, 128>>>(Wp1, bp1, Wp2, bp2);
    sortA_hist<<<128, 128>>>(lengths);
    sortB_scan<<<1, 128>>>();
    sortC_scatter<<<128, 128>>>(lengths);
    gru_mma_kernel<<<128, 256, GRU_SMEM>>>(seqs, lengths, Wih, bih, Whh, bhh, Ws, bs);
    final_kernel<<<1, 128>>>(out);
}